// round 14
// baseline (speedup 1.0000x reference)
#include <cuda_runtime.h>
#include <cuda_fp16.h>
#include <cstdint>
#include <math.h>

// Problem constants
#define BB 64
#define TT 4096
#define DD 256
#define HH 341
#define BT (BB*TT)
#define NEGV (-1e9f)
#define NP 352            // hidden padded to 11*32
#define NCHUNK 11         // 32 n-cols per chunk
#define LSCALE 2048.0f
#define INV_LSCALE (1.0f/2048.0f)

__device__ float g_scores[BT];
__device__ float g_tv[BB];
__device__ int   g_done;            // zero-init; self-resetting each launch
__device__ __align__(16) __half g_w1t_hi[NP*DD];   // W1^T [h][d] fp16 hi
__device__ __align__(16) __half g_w1t_lo[NP*DD];   // fp16 residual * 2048
__device__ __align__(16) float g_w1t32[NP*DD];     // W1^T fp32 (refinement)
__device__ float g_b1p[NP];
__device__ float g_w2p[NP];

// f32-accumulator fp16 MMA
#define MMA16816F(d, a0,a1,a2,a3, b0,b1) \
    asm volatile("mma.sync.aligned.m16n8k16.row.col.f32.f16.f16.f32 " \
        "{%0,%1,%2,%3}, {%4,%5,%6,%7}, {%8,%9}, {%0,%1,%2,%3};" \
        : "+f"((d)[0]), "+f"((d)[1]), "+f"((d)[2]), "+f"((d)[3]) \
        : "r"(a0), "r"(a1), "r"(a2), "r"(a3), "r"(b0), "r"(b1))

// f16-accumulator fp16 MMA (c0 = halves r0,r1; c1 = halves r2,r3)
#define MMA16816H(c0, c1, a0,a1,a2,a3, b0,b1) \
    asm volatile("mma.sync.aligned.m16n8k16.row.col.f16.f16.f16.f16 " \
        "{%0,%1}, {%2,%3,%4,%5}, {%6,%7}, {%0,%1};" \
        : "+r"(c0), "+r"(c1) \
        : "r"(a0), "r"(a1), "r"(a2), "r"(a3), "r"(b0), "r"(b1))

#define LDSM_X4(r0,r1,r2,r3, addr) \
    asm volatile("ldmatrix.sync.aligned.m8n8.x4.shared.b16 {%0,%1,%2,%3}, [%4];" \
        : "=r"(r0), "=r"(r1), "=r"(r2), "=r"(r3) : "r"(addr))

#define CP_ASYNC16(dst, src) \
    asm volatile("cp.async.cg.shared.global [%0], [%1], 16;" :: "r"(dst), "l"(src))
#define CP_COMMIT() asm volatile("cp.async.commit_group;" ::: "memory")
#define CP_WAIT(n)  asm volatile("cp.async.wait_group %0;" :: "n"(n) : "memory")

__device__ __forceinline__ uint32_t smem_u32(const void* p) {
    uint32_t a;
    asm("{ .reg .u64 t; cvta.to.shared.u64 t, %1; cvt.u32.u64 %0, t; }" : "=r"(a) : "l"(p));
    return a;
}
__device__ __forceinline__ uint32_t packh(__half a, __half b) {
    return (uint32_t)__half_as_ushort(a) | ((uint32_t)__half_as_ushort(b) << 16);
}
__device__ __forceinline__ float2 h2f2(uint32_t v) {
    __half2 h = *reinterpret_cast<__half2*>(&v);
    return __half22float2(h);
}
__device__ __forceinline__ float gelu_w2(float v, float w2v) {
    return 0.5f*v*(1.f + erff(v*0.70710678118654752f)) * w2v;
}

// ---------------------------------------------------------------------------
// Prologue: transpose + fp16-split W1 (lo pre-scaled by 2048), pad b1/W2
// ---------------------------------------------------------------------------
__global__ void kernelW(const float* __restrict__ W1, const float* __restrict__ b1,
                        const float* __restrict__ W2)
{
    int h = blockIdx.x;       // 0..351
    int d = threadIdx.x;      // 0..255
    float w = (h < HH) ? W1[d*HH + h] : 0.f;
    __half hi = __float2half_rn(w);
    __half lo = __float2half_rn((w - __half2float(hi)) * LSCALE);
    g_w1t_hi[h*DD + d] = hi;
    g_w1t_lo[h*DD + d] = lo;
    g_w1t32[h*DD + d] = w;
    if (d == 0) {
        g_b1p[h] = (h < HH) ? b1[h] : 0.f;
        g_w2p[h] = (h < HH) ? W2[h] : 0.f;
    }
}

// ---------------------------------------------------------------------------
// Kernel A: 64-token blocks, 2 blocks/SM, fp16 3-term ldmatrix+mma GEMM
// ---------------------------------------------------------------------------
#define RP 528
#define OFF_AHI 0
#define OFF_ALO 33792
#define OFF_B   67584
#define OFF_ATTN 101376
#define OFF_B1P 101632
#define OFF_W2P 103040
#define OFF_SC  104448
#define OFF_ANY 104704
#define SMEM_A_TOT 104768

extern __shared__ char smx[];

__device__ __forceinline__ void stage_B(int c, int tid, uint32_t sb) {
#pragma unroll
    for (int i = 0; i < 8; ++i) {
        int v = tid + i*256;
        int half_ = v >> 10;
        int r = (v >> 5) & 31;
        int u = v & 31;
        const uint4* src = (half_ ? (const uint4*)g_w1t_lo : (const uint4*)g_w1t_hi)
                         + (size_t)(c*32 + r)*32 + u;
        uint32_t dst = sb + OFF_B + half_*16896 + r*RP + u*16;
        CP_ASYNC16(dst, src);
    }
}

__global__ __launch_bounds__(256, 2)
void kernelA(const float* __restrict__ emb, const float* __restrict__ attn,
             const float* __restrict__ gamma_, const float* __restrict__ beta_,
             const float* __restrict__ b2)
{
    const int tid = threadIdx.x, lane = tid & 31, wid = tid >> 5;
    const int base = blockIdx.x * 64;
    uint32_t sb = smem_u32(smx);

    float* s_attn = (float*)(smx + OFF_ATTN);
    float* s_b1p  = (float*)(smx + OFF_B1P);
    float* s_w2p  = (float*)(smx + OFF_W2P);
    float* s_sc   = (float*)(smx + OFF_SC);
    int*   s_any  = (int*)(smx + OFF_ANY);

    if (tid == 0) *s_any = 0;
    __syncthreads();
    if (tid < 64) {
        float a = attn[base + tid];
        s_attn[tid] = a;
        s_sc[tid] = 0.f;
        if (a != 0.f) *s_any = 1;
    }
    __syncthreads();
    if (!*s_any) {
        if (tid < 64) g_scores[base + tid] = NEGV;
        return;
    }

    stage_B(0, tid, sb);
    CP_COMMIT();

    if (tid < NP) s_b1p[tid] = g_b1p[tid], s_w2p[tid] = g_w2p[tid];
    if (tid + 256 < NP) { s_b1p[tid+256] = g_b1p[tid+256]; s_w2p[tid+256] = g_w2p[tid+256]; }

    for (int it = 0; it < 8; ++it) {
        int mt = wid * 8 + it;
        const float4* e4 = (const float4*)(emb + (size_t)(base + mt) * DD);
        float4 va = e4[lane*2], vb = e4[lane*2 + 1];
        float am = s_attn[mt];
        va.x *= am; va.y *= am; va.z *= am; va.w *= am;
        vb.x *= am; vb.y *= am; vb.z *= am; vb.w *= am;
        float s  = va.x+va.y+va.z+va.w+vb.x+vb.y+vb.z+vb.w;
        float s2 = va.x*va.x+va.y*va.y+va.z*va.z+va.w*va.w
                 + vb.x*vb.x+vb.y*vb.y+vb.z*vb.z+vb.w*vb.w;
#pragma unroll
        for (int o = 16; o; o >>= 1) {
            s  += __shfl_xor_sync(0xffffffffu, s, o);
            s2 += __shfl_xor_sync(0xffffffffu, s2, o);
        }
        float mu = s * (1.f/256.f);
        float rstd = rsqrtf(s2 * (1.f/256.f) - mu*mu + 1e-5f);

        float x[8] = {va.x, va.y, va.z, va.w, vb.x, vb.y, vb.z, vb.w};
        uint32_t qh[4], ql[4];
        const int d0 = lane * 8;
#pragma unroll
        for (int p = 0; p < 4; ++p) {
            float x0 = (x[2*p]   - mu) * rstd * gamma_[d0+2*p]   + beta_[d0+2*p];
            float x1 = (x[2*p+1] - mu) * rstd * gamma_[d0+2*p+1] + beta_[d0+2*p+1];
            __half h0 = __float2half_rn(x0);
            __half h1 = __float2half_rn(x1);
            __half l0 = __float2half_rn((x0 - __half2float(h0)) * LSCALE);
            __half l1 = __float2half_rn((x1 - __half2float(h1)) * LSCALE);
            qh[p] = packh(h0, h1);
            ql[p] = packh(l0, l1);
        }
        uint32_t off = mt * RP + lane * 16;
        *(uint4*)(smx + OFF_AHI + off) = make_uint4(qh[0],qh[1],qh[2],qh[3]);
        *(uint4*)(smx + OFF_ALO + off) = make_uint4(ql[0],ql[1],ql[2],ql[3]);
    }

    const int wm = wid & 3;
    const int wn = wid >> 2;
    const int m0 = wm * 16;
    const int g = lane >> 2, q = lane & 3;
    const int lrow = lane & 15;
    const int lcol = (lane >> 4) * 16;

    const uint32_t aAddrHi = sb + OFF_AHI + (m0 + lrow) * RP + lcol;
    const uint32_t aAddrLo = sb + OFF_ALO + (m0 + lrow) * RP + lcol;
    const uint32_t bHi = sb + OFF_B + (wn*16 + lrow) * RP + lcol;
    const uint32_t bLo = bHi + 16896;

    float part0 = 0.f, part1 = 0.f;

    for (int c = 0; c < NCHUNK; ++c) {
        CP_WAIT(0);
        __syncthreads();    // B chunk c visible to all

        float hA0[4] = {0.f,0.f,0.f,0.f};
        float hA1[4] = {0.f,0.f,0.f,0.f};
        uint32_t xA0a = 0u, xA0b = 0u;
        uint32_t xB0a = 0u, xB0b = 0u;
        uint32_t xA1a = 0u, xA1b = 0u;
        uint32_t xB1a = 0u, xB1b = 0u;

#pragma unroll 4
        for (int ks = 0; ks < 16; ++ks) {
            const int kb = ks * 32;
            uint32_t ah0,ah1,ah2,ah3, al0,al1,al2,al3;
            uint32_t bh0,bh1,bh2,bh3, bl0,bl1,bl2,bl3;
            LDSM_X4(ah0,ah1,ah2,ah3, aAddrHi + kb);
            LDSM_X4(al0,al1,al2,al3, aAddrLo + kb);
            LDSM_X4(bh0,bh1,bh2,bh3, bHi + kb);
            LDSM_X4(bl0,bl1,bl2,bl3, bLo + kb);
            MMA16816F(hA0, ah0,ah1,ah2,ah3, bh0,bh2);
            MMA16816H(xA0a,xA0b, ah0,ah1,ah2,ah3, bl0,bl2);
            MMA16816H(xB0a,xB0b, al0,al1,al2,al3, bh0,bh2);
            MMA16816F(hA1, ah0,ah1,ah2,ah3, bh1,bh3);
            MMA16816H(xA1a,xA1b, ah0,ah1,ah2,ah3, bl1,bl3);
            MMA16816H(xB1a,xB1b, al0,al1,al2,al3, bh1,bh3);
        }

        // epilogue FIRST (register/constant-only): overlaps other warps' MMA
        {
            float2 pA0 = h2f2(xA0a), pA0b = h2f2(xA0b);
            float2 pB0 = h2f2(xB0a), pB0b = h2f2(xB0b);
            float2 pA1 = h2f2(xA1a), pA1b = h2f2(xA1b);
            float2 pB1 = h2f2(xB1a), pB1b = h2f2(xB1b);
            float acc0[4], acc1[4];
            acc0[0] = hA0[0] + (pA0.x  + pB0.x ) * INV_LSCALE;
            acc0[1] = hA0[1] + (pA0.y  + pB0.y ) * INV_LSCALE;
            acc0[2] = hA0[2] + (pA0b.x + pB0b.x) * INV_LSCALE;
            acc0[3] = hA0[3] + (pA0b.y + pB0b.y) * INV_LSCALE;
            acc1[0] = hA1[0] + (pA1.x  + pB1.x ) * INV_LSCALE;
            acc1[1] = hA1[1] + (pA1.y  + pB1.y ) * INV_LSCALE;
            acc1[2] = hA1[2] + (pA1b.x + pB1b.x) * INV_LSCALE;
            acc1[3] = hA1[3] + (pA1b.y + pB1b.y) * INV_LSCALE;

            int hb = c*32 + wn*16 + 2*q;
            float b1a = s_b1p[hb],   w2a = s_w2p[hb];
            float b1b = s_b1p[hb+1], w2b = s_w2p[hb+1];
            part0 += gelu_w2(acc0[0] + b1a, w2a) + gelu_w2(acc0[1] + b1b, w2b);
            part1 += gelu_w2(acc0[2] + b1a, w2a) + gelu_w2(acc0[3] + b1b, w2b);
            int hc = hb + 8;
            float b1c = s_b1p[hc],   w2c = s_w2p[hc];
            float b1d = s_b1p[hc+1], w2d = s_w2p[hc+1];
            part0 += gelu_w2(acc1[0] + b1c, w2c) + gelu_w2(acc1[1] + b1d, w2d);
            part1 += gelu_w2(acc1[2] + b1c, w2c) + gelu_w2(acc1[3] + b1d, w2d);
        }

        __syncthreads();    // all warps done reading buf before restage
        if (c + 1 < NCHUNK) { stage_B(c+1, tid, sb); CP_COMMIT(); }
    }

    part0 += __shfl_xor_sync(0xffffffffu, part0, 1);
    part0 += __shfl_xor_sync(0xffffffffu, part0, 2);
    part1 += __shfl_xor_sync(0xffffffffu, part1, 1);
    part1 += __shfl_xor_sync(0xffffffffu, part1, 2);
    if (q == 0) {
        atomicAdd(&s_sc[m0 + g], part0);
        atomicAdd(&s_sc[m0 + g + 8], part1);
    }
    __syncthreads();
    if (tid < 64) {
        float sc = s_sc[tid] + b2[0];
        if (s_attn[tid] == 0.f) sc = NEGV;
        g_scores[base + tid] = sc;
    }
}

// ---------------------------------------------------------------------------
// Threefry-2x32-20, JAX partitionable: ctr=(0,i), draw = out0 ^ out1
// ---------------------------------------------------------------------------
__device__ __forceinline__ uint32_t rotl32(uint32_t x, int r) { return (x << r) | (x >> (32 - r)); }
__device__ __forceinline__ void tf_r4(uint32_t& x0, uint32_t& x1, int a, int b, int c, int d) {
    x0 += x1; x1 = rotl32(x1, a); x1 ^= x0;
    x0 += x1; x1 = rotl32(x1, b); x1 ^= x0;
    x0 += x1; x1 = rotl32(x1, c); x1 ^= x0;
    x0 += x1; x1 = rotl32(x1, d); x1 ^= x0;
}
__device__ __forceinline__ uint32_t jax_bits(uint32_t i) {
    const uint32_t k0 = 0u, k1 = 42u;
    const uint32_t k2 = k0 ^ k1 ^ 0x1BD11BDAu;
    uint32_t x0 = 0u + k0;
    uint32_t x1 = i  + k1;
    tf_r4(x0, x1, 13, 15, 26, 6);   x0 += k1; x1 += k2 + 1u;
    tf_r4(x0, x1, 17, 29, 16, 24);  x0 += k2; x1 += k0 + 2u;
    tf_r4(x0, x1, 13, 15, 26, 6);   x0 += k0; x1 += k1 + 3u;
    tf_r4(x0, x1, 17, 29, 16, 24);  x0 += k1; x1 += k2 + 4u;
    tf_r4(x0, x1, 13, 15, 26, 6);   x0 += k2; x1 += k0 + 5u;
    return x0 ^ x1;
}
__device__ __forceinline__ float gumbel_of(uint32_t lin) {
    uint32_t bits = jax_bits(lin);
    float u = __uint_as_float((bits >> 9) | 0x3f800000u) - 1.0f;
    u = fmaxf(u, 0.f);
    return -logf(-logf(u + 1e-6f) + 1e-6f);
}

// ---------------------------------------------------------------------------
// Kernel B: entmax1.5 bisection + radix-select top-k + exact refinement + TV
// Last block also reduces g_tv -> reg (kernelC folded in).
// ---------------------------------------------------------------------------
#define EPS_W 1.5e-4f
#define MAXC 64
#define SMEM_B ((4*4096 + 32*256)*4)

__global__ __launch_bounds__(1024, 1)
void kernelB(const float* __restrict__ attn, const float* __restrict__ emb,
             const float* __restrict__ gamma_, const float* __restrict__ beta_,
             const float* __restrict__ b2, float* __restrict__ out)
{
    extern __shared__ float sm[];
    float* s_scores = sm;             // 4096
    float* s_attn   = sm + 4096;      // 4096
    float* s_cum    = sm + 8192;      // 4096 (pert)
    float* s_g      = sm + 12288;     // 4096 (g staging for TV)
    float* s_xn     = sm + 16384;     // [32 warps][256]
    __shared__ float red[32], red2[32], red3[32];
    __shared__ float sh_mx, sh_teff, sh_tau, sh_thr, sh_S;
    __shared__ int sh_above, sh_ncand;
    __shared__ int hist[256];
    __shared__ uint32_t sh_prefix;
    __shared__ int sh_remain;
    __shared__ int cand_idx[MAXC];
    __shared__ float cand_pert[MAXC];
    __shared__ int cand_sel[MAXC];

    const int row = blockIdx.x;
    const int tid = threadIdx.x;
    const int lane = tid & 31, wid = tid >> 5;
    const int p0 = tid * 4;

    // ---- load + t_eff + row max
    float tf_ = 0.f, mx = -3.402823466e38f;
    for (int t = tid; t < TT; t += 1024) {
        float s = g_scores[row*TT + t];
        float a = attn[row*TT + t];
        s_scores[t] = s; s_attn[t] = a;
        tf_ += a; mx = fmaxf(mx, s);
    }
    for (int o = 16; o; o >>= 1) {
        tf_ += __shfl_xor_sync(0xffffffffu, tf_, o);
        mx = fmaxf(mx, __shfl_xor_sync(0xffffffffu, mx, o));
    }
    if (lane == 0) { red[wid] = tf_; red2[wid] = mx; }
    __syncthreads();
    if (tid == 0) {
        float a = 0.f, b = -3.402823466e38f;
        for (int w = 0; w < 32; w++) { a += red[w]; b = fmaxf(b, red2[w]); }
        sh_teff = a; sh_mx = b;
        sh_above = 0; sh_ncand = 0;
    }
    __syncthreads();
    mx = sh_mx;

    // ---- entmax tau via bisection on f(tau) = sum max(x-tau,0)^2 (dec.)
    float xr[4];
#pragma unroll
    for (int j = 0; j < 4; ++j) xr[j] = (s_scores[p0+j] - mx) * 0.5f;

    float lo = -1.0f, hi = 0.0f;
    for (int it = 0; it < 28; ++it) {
        float tau = 0.5f*(lo + hi);
        float ssum = 0.f;
#pragma unroll
        for (int j = 0; j < 4; ++j) {
            float d = fmaxf(xr[j] - tau, 0.f);
            ssum += d*d;
        }
        for (int o = 16; o; o >>= 1) ssum += __shfl_xor_sync(0xffffffffu, ssum, o);
        if (lane == 0) red[wid] = ssum;
        __syncthreads();
        if (tid == 0) {
            float a = 0.f;
            for (int w = 0; w < 32; w++) a += red[w];
            sh_S = a;
        }
        __syncthreads();
        if (sh_S > 1.f) lo = tau; else hi = tau;
    }
    // support stats over {x > tau_b}, then exact tau* from the support set
    {
        float taub = 0.5f*(lo + hi);
        float c = 0.f, S1 = 0.f, S2 = 0.f;
#pragma unroll
        for (int j = 0; j < 4; ++j) {
            if (xr[j] > taub) { c += 1.f; S1 += xr[j]; S2 += xr[j]*xr[j]; }
        }
        for (int o = 16; o; o >>= 1) {
            c  += __shfl_xor_sync(0xffffffffu, c, o);
            S1 += __shfl_xor_sync(0xffffffffu, S1, o);
            S2 += __shfl_xor_sync(0xffffffffu, S2, o);
        }
        if (lane == 0) { red[wid] = c; red2[wid] = S1; red3[wid] = S2; }
        __syncthreads();
        if (tid == 0) {
            float cc = 0.f, a1 = 0.f, a2 = 0.f;
            for (int w = 0; w < 32; w++) { cc += red[w]; a1 += red2[w]; a2 += red3[w]; }
            float rho = fmaxf(cc, 1.f);
            float mean = a1 / rho;
            float msq  = a2 / rho;
            float ssv  = rho * (msq - mean*mean);
            float delta = (1.f - ssv) / rho;
            sh_tau = mean - sqrtf(fmaxf(delta, 0.f));
        }
        __syncthreads();
    }
    const float taustar = sh_tau;

    // ---- z output
#pragma unroll
    for (int j = 0; j < 4; ++j) {
        float dd = fmaxf(xr[j] - taustar, 0.f);
        out[row*TT + p0 + j] = dd*dd*s_attn[p0+j];
    }

    // ---- gumbel-perturbed scores (+ radix keys in registers)
    uint32_t ur[4];
#pragma unroll
    for (int j = 0; j < 4; ++j) {
        int t = p0 + j;
        float gum = gumbel_of((uint32_t)(row*TT + t));
        float pert = s_scores[t] * s_attn[t] + gum;
        s_cum[t] = pert;
        uint32_t b = __float_as_uint(pert);
        ur[j] = (pert != pert) ? 0u
              : (b ^ ((b >> 31) ? 0xFFFFFFFFu : 0x80000000u));
    }

    const float teff = sh_teff;
    float kf = rintf(0.3f * teff);
    kf = fminf(fmaxf(kf, 1.f), fmaxf(teff, 1.f));
    const int ki = (int)kf;

    // ---- radix select: exact ki-th largest pert (MSB-first, 8 bits/round)
    if (tid == 0) { sh_prefix = 0u; sh_remain = ki; }
    __syncthreads();
    for (int sha = 24; sha >= 0; sha -= 8) {
        if (tid < 256) hist[tid] = 0;
        __syncthreads();
        uint32_t pref = sh_prefix;
#pragma unroll
        for (int j = 0; j < 4; ++j) {
            uint32_t u = ur[j];
            bool match = (sha == 24) || ((u >> (sha + 8)) == pref);
            if (match) atomicAdd(&hist[(u >> sha) & 255], 1);
        }
        __syncthreads();
        if (wid == 0) {
            int b0 = 255 - lane*8;
            int cnt[8];
            int s = 0;
#pragma unroll
            for (int i = 0; i < 8; i++) { cnt[i] = hist[b0 - i]; s += cnt[i]; }
            int pre = s;
            for (int o = 1; o < 32; o <<= 1) {
                int n = __shfl_up_sync(0xffffffffu, pre, o);
                if (lane >= o) pre += n;
            }
            int excl = pre - s;
            int rem = sh_remain;
            if (excl < rem && rem <= excl + s) {
                int acc = excl;
#pragma unroll
                for (int i = 0; i < 8; i++) {
                    if (acc + cnt[i] >= rem) {
                        uint32_t oldp = sh_prefix;
                        sh_prefix = (oldp << 8) | (uint32_t)(b0 - i);
                        sh_remain = rem - acc;
                        break;
                    }
                    acc += cnt[i];
                }
            }
        }
        __syncthreads();
    }
    if (tid == 0) {
        uint32_t su = sh_prefix;
        uint32_t tb = (su & 0x80000000u) ? (su ^ 0x80000000u) : ~su;
        sh_thr = __uint_as_float(tb);
    }
    __syncthreads();
    const float thr = sh_thr;
    const float hiW = thr + EPS_W, loW = thr - EPS_W;

    // ---- classification counts + candidate gather
    {
        int my_above = 0;
#pragma unroll
        for (int j = 0; j < 4; ++j) {
            int t = p0 + j;
            float p = s_cum[t];
            if (p > hiW) my_above++;
            else if (p >= loW) {
                int pos = atomicAdd(&sh_ncand, 1);
                if (pos < MAXC) cand_idx[pos] = t;
            }
        }
        for (int o = 16; o; o >>= 1) my_above += __shfl_xor_sync(0xffffffffu, my_above, o);
        if (lane == 0) atomicAdd(&sh_above, my_above);
    }
    __syncthreads();
    const int ncand = sh_ncand;
    const bool refine = (ncand <= MAXC);

    // ---- exact recompute of candidate perts (warp per candidate)
    if (refine) {
        const float b2v = b2[0];
        for (int c = wid; c < ncand; c += 32) {
            int t = cand_idx[c];
            float ex;
            if (s_attn[t] == 0.f) {
                ex = s_cum[t];
            } else {
                const float4* e4 = (const float4*)(emb + ((size_t)row*TT + t)*DD);
                float4 va = e4[lane*2], vb = e4[lane*2+1];
                float s  = va.x+va.y+va.z+va.w+vb.x+vb.y+vb.z+vb.w;
                float s2 = va.x*va.x+va.y*va.y+va.z*va.z+va.w*va.w
                         + vb.x*vb.x+vb.y*vb.y+vb.z*vb.z+vb.w*vb.w;
#pragma unroll
                for (int o = 16; o; o >>= 1) {
                    s  += __shfl_xor_sync(0xffffffffu, s, o);
                    s2 += __shfl_xor_sync(0xffffffffu, s2, o);
                }
                float mu = s * (1.f/256.f);
                float rstd = rsqrtf(s2 * (1.f/256.f) - mu*mu + 1e-5f);
                float xv[8] = {va.x,va.y,va.z,va.w,vb.x,vb.y,vb.z,vb.w};
                float* xw = s_xn + wid*256 + lane*8;
#pragma unroll
                for (int p = 0; p < 8; ++p) {
                    int d = lane*8 + p;
                    xw[p] = (xv[p] - mu) * rstd * gamma_[d] + beta_[d];
                }
                __syncwarp();
                float sc = 0.f;
                for (int h = lane; h < HH; h += 32) {
                    const float4* wr = (const float4*)(g_w1t32 + (size_t)h*DD);
                    const float4* xq = (const float4*)(s_xn + wid*256);
                    float dot = 0.f;
#pragma unroll 8
                    for (int u = 0; u < 64; ++u) {
                        float4 a = wr[u], bq = xq[u];
                        dot += a.x*bq.x + a.y*bq.y + a.z*bq.z + a.w*bq.w;
                    }
                    float v = dot + g_b1p[h];
                    sc += gelu_w2(v, g_w2p[h]);
                }
#pragma unroll
                for (int o = 16; o; o >>= 1) sc += __shfl_xor_sync(0xffffffffu, sc, o);
                ex = sc + b2v + gumbel_of((uint32_t)(row*TT + t));
                __syncwarp();
            }
            if (lane == 0) cand_pert[c] = ex;
        }
    }
    __syncthreads();

    if (refine && tid == 0) {
        int need = ki - sh_above;
        for (int c = 0; c < ncand; ++c) {
            int rank = 0;
            float pc = cand_pert[c];
            for (int c2 = 0; c2 < ncand; ++c2)
                if (cand_pert[c2] > pc) rank++;
            cand_sel[c] = (rank < need) ? 1 : 0;
        }
    }
    __syncthreads();

    // ---- g output
#pragma unroll
    for (int j = 0; j < 4; ++j) {
        int t = p0 + j;
        float p = s_cum[t];
        float a0 = s_attn[t];
        float gv;
        if (refine) {
            if (p > hiW) gv = a0;
            else if (p >= loW) {
                gv = 0.f;
                for (int c = 0; c < ncand; ++c)
                    if (cand_idx[c] == t) { gv = cand_sel[c] ? a0 : 0.f; break; }
            } else gv = 0.f;
        } else {
            gv = (p >= thr) ? a0 : 0.f;
        }
        out[BT + row*TT + t] = gv;
        s_g[t] = gv;
    }
    __syncthreads();

    // ---- TV
    float num = 0.f, den = 0.f;
    for (int t = tid; t < TT - 1; t += 1024) {
        float valid = s_attn[t] * s_attn[t+1];
        num += fabsf(s_g[t+1] - s_g[t]) * valid;
        den += valid;
    }
    for (int o = 16; o; o >>= 1) {
        num += __shfl_xor_sync(0xffffffffu, num, o);
        den += __shfl_xor_sync(0xffffffffu, den, o);
    }
    if (lane == 0) { red[wid] = num; red2[wid] = den; }
    __syncthreads();
    if (tid == 0) {
        float a = 0.f, b = 0.f;
        for (int w = 0; w < 32; w++) { a += red[w]; b += red2[w]; }
        g_tv[row] = a / fmaxf(b, 1.f);
        __threadfence();
        int n = atomicAdd(&g_done, 1);
        if (n == BB - 1) {           // last block: reduce + reset counter
            __threadfence();
            float s = 0.f;
            for (int r = 0; r < BB; r++) s += g_tv[r];
            out[2*BT] = 0.1f * (s / (float)BB);
            atomicExch(&g_done, 0);  // replay-deterministic reset
        }
    }
}

extern "C" void kernel_launch(void* const* d_in, const int* in_sizes, int n_in,
                              void* d_out, int out_size)
{
    const float* emb   = (const float*)d_in[0];
    const float* attn  = (const float*)d_in[1];
    const float* gamma = (const float*)d_in[2];
    const float* beta  = (const float*)d_in[3];
    const float* W1    = (const float*)d_in[4];
    const float* b1    = (const float*)d_in[5];
    const float* W2    = (const float*)d_in[6];
    const float* b2    = (const float*)d_in[7];
    float* out = (float*)d_out;

    cudaFuncSetAttribute(kernelA, cudaFuncAttributeMaxDynamicSharedMemorySize, SMEM_A_TOT);
    cudaFuncSetAttribute(kernelB, cudaFuncAttributeMaxDynamicSharedMemorySize, SMEM_B);

    kernelW<<<NP, 256>>>(W1, b1, W2);
    kernelA<<<BT/64, 256, SMEM_A_TOT>>>(emb, attn, gamma, beta, b2);
    kernelB<<<BB, 1024, SMEM_B>>>(attn, emb, gamma, beta, b2, out);
}

// round 15
// speedup vs baseline: 1.0309x; 1.0309x over previous
#include <cuda_runtime.h>
#include <cuda_fp16.h>
#include <cstdint>
#include <math.h>

// Problem constants
#define BB 64
#define TT 4096
#define DD 256
#define HH 341
#define BT (BB*TT)
#define NEGV (-1e9f)
#define NP 352            // hidden padded to 11*32
#define NCHUNK 11         // 32 n-cols per chunk
#define LSCALE 2048.0f
#define INV_LSCALE (1.0f/2048.0f)

__device__ float g_scores[BT];
__device__ float g_tv[BB];
__device__ int   g_done;            // zero-init; self-resetting each launch
__device__ __align__(16) __half g_w1t_hi[NP*DD];   // W1^T [h][d] fp16 hi
__device__ __align__(16) __half g_w1t_lo[NP*DD];   // fp16 residual * 2048
__device__ __align__(16) float g_w1t32[NP*DD];     // W1^T fp32 (refinement)
__device__ float g_b1p[NP];
__device__ float g_w2p[NP];

// f32-accumulator fp16 MMA
#define MMA16816F(d, a0,a1,a2,a3, b0,b1) \
    asm volatile("mma.sync.aligned.m16n8k16.row.col.f32.f16.f16.f32 " \
        "{%0,%1,%2,%3}, {%4,%5,%6,%7}, {%8,%9}, {%0,%1,%2,%3};" \
        : "+f"((d)[0]), "+f"((d)[1]), "+f"((d)[2]), "+f"((d)[3]) \
        : "r"(a0), "r"(a1), "r"(a2), "r"(a3), "r"(b0), "r"(b1))

// f16-accumulator fp16 MMA (c0 = halves r0,r1; c1 = halves r2,r3)
#define MMA16816H(c0, c1, a0,a1,a2,a3, b0,b1) \
    asm volatile("mma.sync.aligned.m16n8k16.row.col.f16.f16.f16.f16 " \
        "{%0,%1}, {%2,%3,%4,%5}, {%6,%7}, {%0,%1};" \
        : "+r"(c0), "+r"(c1) \
        : "r"(a0), "r"(a1), "r"(a2), "r"(a3), "r"(b0), "r"(b1))

#define LDSM_X4(r0,r1,r2,r3, addr) \
    asm volatile("ldmatrix.sync.aligned.m8n8.x4.shared.b16 {%0,%1,%2,%3}, [%4];" \
        : "=r"(r0), "=r"(r1), "=r"(r2), "=r"(r3) : "r"(addr))

#define CP_ASYNC16(dst, src) \
    asm volatile("cp.async.cg.shared.global [%0], [%1], 16;" :: "r"(dst), "l"(src))
#define CP_COMMIT() asm volatile("cp.async.commit_group;" ::: "memory")
#define CP_WAIT(n)  asm volatile("cp.async.wait_group %0;" :: "n"(n) : "memory")

__device__ __forceinline__ uint32_t smem_u32(const void* p) {
    uint32_t a;
    asm("{ .reg .u64 t; cvta.to.shared.u64 t, %1; cvt.u32.u64 %0, t; }" : "=r"(a) : "l"(p));
    return a;
}
__device__ __forceinline__ uint32_t packh(__half a, __half b) {
    return (uint32_t)__half_as_ushort(a) | ((uint32_t)__half_as_ushort(b) << 16);
}
__device__ __forceinline__ float2 h2f2(uint32_t v) {
    __half2 h = *reinterpret_cast<__half2*>(&v);
    return __half22float2(h);
}
__device__ __forceinline__ float gelu_w2(float v, float w2v) {
    return 0.5f*v*(1.f + erff(v*0.70710678118654752f)) * w2v;
}

// ---------------------------------------------------------------------------
// Prologue: transpose + fp16-split W1 (lo pre-scaled by 2048), pad b1/W2
// ---------------------------------------------------------------------------
__global__ void kernelW(const float* __restrict__ W1, const float* __restrict__ b1,
                        const float* __restrict__ W2)
{
    int h = blockIdx.x;       // 0..351
    int d = threadIdx.x;      // 0..255
    float w = (h < HH) ? W1[d*HH + h] : 0.f;
    __half hi = __float2half_rn(w);
    __half lo = __float2half_rn((w - __half2float(hi)) * LSCALE);
    g_w1t_hi[h*DD + d] = hi;
    g_w1t_lo[h*DD + d] = lo;
    g_w1t32[h*DD + d] = w;
    if (d == 0) {
        g_b1p[h] = (h < HH) ? b1[h] : 0.f;
        g_w2p[h] = (h < HH) ? W2[h] : 0.f;
    }
}

// ---------------------------------------------------------------------------
// Kernel A: 64-token blocks, 2 blocks/SM, fp16 3-term ldmatrix+mma GEMM
// Loop order (R13-proven): mma -> sync -> restage(c+1) -> epilogue, so the
// erff epilogue overlaps the cp.async flight of the next B chunk.
// ---------------------------------------------------------------------------
#define RP 528
#define OFF_AHI 0
#define OFF_ALO 33792
#define OFF_B   67584
#define OFF_ATTN 101376
#define OFF_B1P 101632
#define OFF_W2P 103040
#define OFF_SC  104448
#define OFF_ANY 104704
#define SMEM_A_TOT 104768

extern __shared__ char smx[];

__device__ __forceinline__ void stage_B(int c, int tid, uint32_t sb) {
#pragma unroll
    for (int i = 0; i < 8; ++i) {
        int v = tid + i*256;
        int half_ = v >> 10;
        int r = (v >> 5) & 31;
        int u = v & 31;
        const uint4* src = (half_ ? (const uint4*)g_w1t_lo : (const uint4*)g_w1t_hi)
                         + (size_t)(c*32 + r)*32 + u;
        uint32_t dst = sb + OFF_B + half_*16896 + r*RP + u*16;
        CP_ASYNC16(dst, src);
    }
}

__global__ __launch_bounds__(256, 2)
void kernelA(const float* __restrict__ emb, const float* __restrict__ attn,
             const float* __restrict__ gamma_, const float* __restrict__ beta_,
             const float* __restrict__ b2)
{
    const int tid = threadIdx.x, lane = tid & 31, wid = tid >> 5;
    const int base = blockIdx.x * 64;
    uint32_t sb = smem_u32(smx);

    float* s_attn = (float*)(smx + OFF_ATTN);
    float* s_b1p  = (float*)(smx + OFF_B1P);
    float* s_w2p  = (float*)(smx + OFF_W2P);
    float* s_sc   = (float*)(smx + OFF_SC);
    int*   s_any  = (int*)(smx + OFF_ANY);

    if (tid == 0) *s_any = 0;
    __syncthreads();
    if (tid < 64) {
        float a = attn[base + tid];
        s_attn[tid] = a;
        s_sc[tid] = 0.f;
        if (a != 0.f) *s_any = 1;
    }
    __syncthreads();
    if (!*s_any) {
        if (tid < 64) g_scores[base + tid] = NEGV;
        return;
    }

    stage_B(0, tid, sb);
    CP_COMMIT();

    if (tid < NP) s_b1p[tid] = g_b1p[tid], s_w2p[tid] = g_w2p[tid];
    if (tid + 256 < NP) { s_b1p[tid+256] = g_b1p[tid+256]; s_w2p[tid+256] = g_w2p[tid+256]; }

    for (int it = 0; it < 8; ++it) {
        int mt = wid * 8 + it;
        const float4* e4 = (const float4*)(emb + (size_t)(base + mt) * DD);
        float4 va = e4[lane*2], vb = e4[lane*2 + 1];
        float am = s_attn[mt];
        va.x *= am; va.y *= am; va.z *= am; va.w *= am;
        vb.x *= am; vb.y *= am; vb.z *= am; vb.w *= am;
        float s  = va.x+va.y+va.z+va.w+vb.x+vb.y+vb.z+vb.w;
        float s2 = va.x*va.x+va.y*va.y+va.z*va.z+va.w*va.w
                 + vb.x*vb.x+vb.y*vb.y+vb.z*vb.z+vb.w*vb.w;
#pragma unroll
        for (int o = 16; o; o >>= 1) {
            s  += __shfl_xor_sync(0xffffffffu, s, o);
            s2 += __shfl_xor_sync(0xffffffffu, s2, o);
        }
        float mu = s * (1.f/256.f);
        float rstd = rsqrtf(s2 * (1.f/256.f) - mu*mu + 1e-5f);

        float x[8] = {va.x, va.y, va.z, va.w, vb.x, vb.y, vb.z, vb.w};
        uint32_t qh[4], ql[4];
        const int d0 = lane * 8;
#pragma unroll
        for (int p = 0; p < 4; ++p) {
            float x0 = (x[2*p]   - mu) * rstd * gamma_[d0+2*p]   + beta_[d0+2*p];
            float x1 = (x[2*p+1] - mu) * rstd * gamma_[d0+2*p+1] + beta_[d0+2*p+1];
            __half h0 = __float2half_rn(x0);
            __half h1 = __float2half_rn(x1);
            __half l0 = __float2half_rn((x0 - __half2float(h0)) * LSCALE);
            __half l1 = __float2half_rn((x1 - __half2float(h1)) * LSCALE);
            qh[p] = packh(h0, h1);
            ql[p] = packh(l0, l1);
        }
        uint32_t off = mt * RP + lane * 16;
        *(uint4*)(smx + OFF_AHI + off) = make_uint4(qh[0],qh[1],qh[2],qh[3]);
        *(uint4*)(smx + OFF_ALO + off) = make_uint4(ql[0],ql[1],ql[2],ql[3]);
    }

    const int wm = wid & 3;
    const int wn = wid >> 2;
    const int m0 = wm * 16;
    const int g = lane >> 2, q = lane & 3;
    const int lrow = lane & 15;
    const int lcol = (lane >> 4) * 16;

    const uint32_t aAddrHi = sb + OFF_AHI + (m0 + lrow) * RP + lcol;
    const uint32_t aAddrLo = sb + OFF_ALO + (m0 + lrow) * RP + lcol;
    const uint32_t bHi = sb + OFF_B + (wn*16 + lrow) * RP + lcol;
    const uint32_t bLo = bHi + 16896;

    float part0 = 0.f, part1 = 0.f;

    for (int c = 0; c < NCHUNK; ++c) {
        CP_WAIT(0);
        __syncthreads();    // B chunk c visible to all

        float hA0[4] = {0.f,0.f,0.f,0.f};
        float hA1[4] = {0.f,0.f,0.f,0.f};
        uint32_t xA0a = 0u, xA0b = 0u;
        uint32_t xB0a = 0u, xB0b = 0u;
        uint32_t xA1a = 0u, xA1b = 0u;
        uint32_t xB1a = 0u, xB1b = 0u;

#pragma unroll 4
        for (int ks = 0; ks < 16; ++ks) {
            const int kb = ks * 32;
            uint32_t ah0,ah1,ah2,ah3, al0,al1,al2,al3;
            uint32_t bh0,bh1,bh2,bh3, bl0,bl1,bl2,bl3;
            LDSM_X4(ah0,ah1,ah2,ah3, aAddrHi + kb);
            LDSM_X4(al0,al1,al2,al3, aAddrLo + kb);
            LDSM_X4(bh0,bh1,bh2,bh3, bHi + kb);
            LDSM_X4(bl0,bl1,bl2,bl3, bLo + kb);
            MMA16816F(hA0, ah0,ah1,ah2,ah3, bh0,bh2);
            MMA16816H(xA0a,xA0b, ah0,ah1,ah2,ah3, bl0,bl2);
            MMA16816H(xB0a,xB0b, al0,al1,al2,al3, bh0,bh2);
            MMA16816F(hA1, ah0,ah1,ah2,ah3, bh1,bh3);
            MMA16816H(xA1a,xA1b, ah0,ah1,ah2,ah3, bl1,bl3);
            MMA16816H(xB1a,xB1b, al0,al1,al2,al3, bh1,bh3);
        }

        __syncthreads();    // all warps done reading buf before restage
        if (c + 1 < NCHUNK) { stage_B(c+1, tid, sb); CP_COMMIT(); }

        // epilogue overlaps the cp.async flight of chunk c+1
        {
            float2 pA0 = h2f2(xA0a), pA0b = h2f2(xA0b);
            float2 pB0 = h2f2(xB0a), pB0b = h2f2(xB0b);
            float2 pA1 = h2f2(xA1a), pA1b = h2f2(xA1b);
            float2 pB1 = h2f2(xB1a), pB1b = h2f2(xB1b);
            float acc0[4], acc1[4];
            acc0[0] = hA0[0] + (pA0.x  + pB0.x ) * INV_LSCALE;
            acc0[1] = hA0[1] + (pA0.y  + pB0.y ) * INV_LSCALE;
            acc0[2] = hA0[2] + (pA0b.x + pB0b.x) * INV_LSCALE;
            acc0[3] = hA0[3] + (pA0b.y + pB0b.y) * INV_LSCALE;
            acc1[0] = hA1[0] + (pA1.x  + pB1.x ) * INV_LSCALE;
            acc1[1] = hA1[1] + (pA1.y  + pB1.y ) * INV_LSCALE;
            acc1[2] = hA1[2] + (pA1b.x + pB1b.x) * INV_LSCALE;
            acc1[3] = hA1[3] + (pA1b.y + pB1b.y) * INV_LSCALE;

            int hb = c*32 + wn*16 + 2*q;
            float b1a = s_b1p[hb],   w2a = s_w2p[hb];
            float b1b = s_b1p[hb+1], w2b = s_w2p[hb+1];
            part0 += gelu_w2(acc0[0] + b1a, w2a) + gelu_w2(acc0[1] + b1b, w2b);
            part1 += gelu_w2(acc0[2] + b1a, w2a) + gelu_w2(acc0[3] + b1b, w2b);
            int hc = hb + 8;
            float b1c = s_b1p[hc],   w2c = s_w2p[hc];
            float b1d = s_b1p[hc+1], w2d = s_w2p[hc+1];
            part0 += gelu_w2(acc1[0] + b1c, w2c) + gelu_w2(acc1[1] + b1d, w2d);
            part1 += gelu_w2(acc1[2] + b1c, w2c) + gelu_w2(acc1[3] + b1d, w2d);
        }
    }

    part0 += __shfl_xor_sync(0xffffffffu, part0, 1);
    part0 += __shfl_xor_sync(0xffffffffu, part0, 2);
    part1 += __shfl_xor_sync(0xffffffffu, part1, 1);
    part1 += __shfl_xor_sync(0xffffffffu, part1, 2);
    if (q == 0) {
        atomicAdd(&s_sc[m0 + g], part0);
        atomicAdd(&s_sc[m0 + g + 8], part1);
    }
    __syncthreads();
    if (tid < 64) {
        float sc = s_sc[tid] + b2[0];
        if (s_attn[tid] == 0.f) sc = NEGV;
        g_scores[base + tid] = sc;
    }
}

// ---------------------------------------------------------------------------
// Threefry-2x32-20, JAX partitionable: ctr=(0,i), draw = out0 ^ out1
// ---------------------------------------------------------------------------
__device__ __forceinline__ uint32_t rotl32(uint32_t x, int r) { return (x << r) | (x >> (32 - r)); }
__device__ __forceinline__ void tf_r4(uint32_t& x0, uint32_t& x1, int a, int b, int c, int d) {
    x0 += x1; x1 = rotl32(x1, a); x1 ^= x0;
    x0 += x1; x1 = rotl32(x1, b); x1 ^= x0;
    x0 += x1; x1 = rotl32(x1, c); x1 ^= x0;
    x0 += x1; x1 = rotl32(x1, d); x1 ^= x0;
}
__device__ __forceinline__ uint32_t jax_bits(uint32_t i) {
    const uint32_t k0 = 0u, k1 = 42u;
    const uint32_t k2 = k0 ^ k1 ^ 0x1BD11BDAu;
    uint32_t x0 = 0u + k0;
    uint32_t x1 = i  + k1;
    tf_r4(x0, x1, 13, 15, 26, 6);   x0 += k1; x1 += k2 + 1u;
    tf_r4(x0, x1, 17, 29, 16, 24);  x0 += k2; x1 += k0 + 2u;
    tf_r4(x0, x1, 13, 15, 26, 6);   x0 += k0; x1 += k1 + 3u;
    tf_r4(x0, x1, 17, 29, 16, 24);  x0 += k1; x1 += k2 + 4u;
    tf_r4(x0, x1, 13, 15, 26, 6);   x0 += k2; x1 += k0 + 5u;
    return x0 ^ x1;
}
__device__ __forceinline__ float gumbel_of(uint32_t lin) {
    uint32_t bits = jax_bits(lin);
    float u = __uint_as_float((bits >> 9) | 0x3f800000u) - 1.0f;
    u = fmaxf(u, 0.f);
    return -logf(-logf(u + 1e-6f) + 1e-6f);
}

// ---------------------------------------------------------------------------
// Kernel B: entmax1.5 bisection + radix-select top-k + exact refinement + TV
// Last block also reduces g_tv -> reg (kernelC folded in).
// ---------------------------------------------------------------------------
#define EPS_W 1.5e-4f
#define MAXC 64
#define SMEM_B ((4*4096 + 32*256)*4)

__global__ __launch_bounds__(1024, 1)
void kernelB(const float* __restrict__ attn, const float* __restrict__ emb,
             const float* __restrict__ gamma_, const float* __restrict__ beta_,
             const float* __restrict__ b2, float* __restrict__ out)
{
    extern __shared__ float sm[];
    float* s_scores = sm;             // 4096
    float* s_attn   = sm + 4096;      // 4096
    float* s_cum    = sm + 8192;      // 4096 (pert)
    float* s_g      = sm + 12288;     // 4096 (g staging for TV)
    float* s_xn     = sm + 16384;     // [32 warps][256]
    __shared__ float red[32], red2[32], red3[32];
    __shared__ float sh_mx, sh_teff, sh_tau, sh_thr, sh_S;
    __shared__ int sh_above, sh_ncand;
    __shared__ int hist[256];
    __shared__ uint32_t sh_prefix;
    __shared__ int sh_remain;
    __shared__ int cand_idx[MAXC];
    __shared__ float cand_pert[MAXC];
    __shared__ int cand_sel[MAXC];

    const int row = blockIdx.x;
    const int tid = threadIdx.x;
    const int lane = tid & 31, wid = tid >> 5;
    const int p0 = tid * 4;

    // ---- load + t_eff + row max
    float tf_ = 0.f, mx = -3.402823466e38f;
    for (int t = tid; t < TT; t += 1024) {
        float s = g_scores[row*TT + t];
        float a = attn[row*TT + t];
        s_scores[t] = s; s_attn[t] = a;
        tf_ += a; mx = fmaxf(mx, s);
    }
    for (int o = 16; o; o >>= 1) {
        tf_ += __shfl_xor_sync(0xffffffffu, tf_, o);
        mx = fmaxf(mx, __shfl_xor_sync(0xffffffffu, mx, o));
    }
    if (lane == 0) { red[wid] = tf_; red2[wid] = mx; }
    __syncthreads();
    if (tid == 0) {
        float a = 0.f, b = -3.402823466e38f;
        for (int w = 0; w < 32; w++) { a += red[w]; b = fmaxf(b, red2[w]); }
        sh_teff = a; sh_mx = b;
        sh_above = 0; sh_ncand = 0;
    }
    __syncthreads();
    mx = sh_mx;

    // ---- entmax tau via bisection on f(tau) = sum max(x-tau,0)^2 (dec.)
    float xr[4];
#pragma unroll
    for (int j = 0; j < 4; ++j) xr[j] = (s_scores[p0+j] - mx) * 0.5f;

    float lo = -1.0f, hi = 0.0f;
    for (int it = 0; it < 28; ++it) {
        float tau = 0.5f*(lo + hi);
        float ssum = 0.f;
#pragma unroll
        for (int j = 0; j < 4; ++j) {
            float d = fmaxf(xr[j] - tau, 0.f);
            ssum += d*d;
        }
        for (int o = 16; o; o >>= 1) ssum += __shfl_xor_sync(0xffffffffu, ssum, o);
        if (lane == 0) red[wid] = ssum;
        __syncthreads();
        if (tid == 0) {
            float a = 0.f;
            for (int w = 0; w < 32; w++) a += red[w];
            sh_S = a;
        }
        __syncthreads();
        if (sh_S > 1.f) lo = tau; else hi = tau;
    }
    // support stats over {x > tau_b}, then exact tau* from the support set
    {
        float taub = 0.5f*(lo + hi);
        float c = 0.f, S1 = 0.f, S2 = 0.f;
#pragma unroll
        for (int j = 0; j < 4; ++j) {
            if (xr[j] > taub) { c += 1.f; S1 += xr[j]; S2 += xr[j]*xr[j]; }
        }
        for (int o = 16; o; o >>= 1) {
            c  += __shfl_xor_sync(0xffffffffu, c, o);
            S1 += __shfl_xor_sync(0xffffffffu, S1, o);
            S2 += __shfl_xor_sync(0xffffffffu, S2, o);
        }
        if (lane == 0) { red[wid] = c; red2[wid] = S1; red3[wid] = S2; }
        __syncthreads();
        if (tid == 0) {
            float cc = 0.f, a1 = 0.f, a2 = 0.f;
            for (int w = 0; w < 32; w++) { cc += red[w]; a1 += red2[w]; a2 += red3[w]; }
            float rho = fmaxf(cc, 1.f);
            float mean = a1 / rho;
            float msq  = a2 / rho;
            float ssv  = rho * (msq - mean*mean);
            float delta = (1.f - ssv) / rho;
            sh_tau = mean - sqrtf(fmaxf(delta, 0.f));
        }
        __syncthreads();
    }
    const float taustar = sh_tau;

    // ---- z output
#pragma unroll
    for (int j = 0; j < 4; ++j) {
        float dd = fmaxf(xr[j] - taustar, 0.f);
        out[row*TT + p0 + j] = dd*dd*s_attn[p0+j];
    }

    // ---- gumbel-perturbed scores (+ radix keys in registers)
    uint32_t ur[4];
#pragma unroll
    for (int j = 0; j < 4; ++j) {
        int t = p0 + j;
        float gum = gumbel_of((uint32_t)(row*TT + t));
        float pert = s_scores[t] * s_attn[t] + gum;
        s_cum[t] = pert;
        uint32_t b = __float_as_uint(pert);
        ur[j] = (pert != pert) ? 0u
              : (b ^ ((b >> 31) ? 0xFFFFFFFFu : 0x80000000u));
    }

    const float teff = sh_teff;
    float kf = rintf(0.3f * teff);
    kf = fminf(fmaxf(kf, 1.f), fmaxf(teff, 1.f));
    const int ki = (int)kf;

    // ---- radix select: exact ki-th largest pert (MSB-first, 8 bits/round)
    if (tid == 0) { sh_prefix = 0u; sh_remain = ki; }
    __syncthreads();
    for (int sha = 24; sha >= 0; sha -= 8) {
        if (tid < 256) hist[tid] = 0;
        __syncthreads();
        uint32_t pref = sh_prefix;
#pragma unroll
        for (int j = 0; j < 4; ++j) {
            uint32_t u = ur[j];
            bool match = (sha == 24) || ((u >> (sha + 8)) == pref);
            if (match) atomicAdd(&hist[(u >> sha) & 255], 1);
        }
        __syncthreads();
        if (wid == 0) {
            int b0 = 255 - lane*8;
            int cnt[8];
            int s = 0;
#pragma unroll
            for (int i = 0; i < 8; i++) { cnt[i] = hist[b0 - i]; s += cnt[i]; }
            int pre = s;
            for (int o = 1; o < 32; o <<= 1) {
                int n = __shfl_up_sync(0xffffffffu, pre, o);
                if (lane >= o) pre += n;
            }
            int excl = pre - s;
            int rem = sh_remain;
            if (excl < rem && rem <= excl + s) {
                int acc = excl;
#pragma unroll
                for (int i = 0; i < 8; i++) {
                    if (acc + cnt[i] >= rem) {
                        uint32_t oldp = sh_prefix;
                        sh_prefix = (oldp << 8) | (uint32_t)(b0 - i);
                        sh_remain = rem - acc;
                        break;
                    }
                    acc += cnt[i];
                }
            }
        }
        __syncthreads();
    }
    if (tid == 0) {
        uint32_t su = sh_prefix;
        uint32_t tb = (su & 0x80000000u) ? (su ^ 0x80000000u) : ~su;
        sh_thr = __uint_as_float(tb);
    }
    __syncthreads();
    const float thr = sh_thr;
    const float hiW = thr + EPS_W, loW = thr - EPS_W;

    // ---- classification counts + candidate gather
    {
        int my_above = 0;
#pragma unroll
        for (int j = 0; j < 4; ++j) {
            int t = p0 + j;
            float p = s_cum[t];
            if (p > hiW) my_above++;
            else if (p >= loW) {
                int pos = atomicAdd(&sh_ncand, 1);
                if (pos < MAXC) cand_idx[pos] = t;
            }
        }
        for (int o = 16; o; o >>= 1) my_above += __shfl_xor_sync(0xffffffffu, my_above, o);
        if (lane == 0) atomicAdd(&sh_above, my_above);
    }
    __syncthreads();
    const int ncand = sh_ncand;
    const bool refine = (ncand <= MAXC);

    // ---- exact recompute of candidate perts (warp per candidate)
    if (refine) {
        const float b2v = b2[0];
        for (int c = wid; c < ncand; c += 32) {
            int t = cand_idx[c];
            float ex;
            if (s_attn[t] == 0.f) {
                ex = s_cum[t];
            } else {
                const float4* e4 = (const float4*)(emb + ((size_t)row*TT + t)*DD);
                float4 va = e4[lane*2], vb = e4[lane*2+1];
                float s  = va.x+va.y+va.z+va.w+vb.x+vb.y+vb.z+vb.w;
                float s2 = va.x*va.x+va.y*va.y+va.z*va.z+va.w*va.w
                         + vb.x*vb.x+vb.y*vb.y+vb.z*vb.z+vb.w*vb.w;
#pragma unroll
                for (int o = 16; o; o >>= 1) {
                    s  += __shfl_xor_sync(0xffffffffu, s, o);
                    s2 += __shfl_xor_sync(0xffffffffu, s2, o);
                }
                float mu = s * (1.f/256.f);
                float rstd = rsqrtf(s2 * (1.f/256.f) - mu*mu + 1e-5f);
                float xv[8] = {va.x,va.y,va.z,va.w,vb.x,vb.y,vb.z,vb.w};
                float* xw = s_xn + wid*256 + lane*8;
#pragma unroll
                for (int p = 0; p < 8; ++p) {
                    int d = lane*8 + p;
                    xw[p] = (xv[p] - mu) * rstd * gamma_[d] + beta_[d];
                }
                __syncwarp();
                float sc = 0.f;
                for (int h = lane; h < HH; h += 32) {
                    const float4* wr = (const float4*)(g_w1t32 + (size_t)h*DD);
                    const float4* xq = (const float4*)(s_xn + wid*256);
                    float dot = 0.f;
#pragma unroll 8
                    for (int u = 0; u < 64; ++u) {
                        float4 a = wr[u], bq = xq[u];
                        dot += a.x*bq.x + a.y*bq.y + a.z*bq.z + a.w*bq.w;
                    }
                    float v = dot + g_b1p[h];
                    sc += gelu_w2(v, g_w2p[h]);
                }
#pragma unroll
                for (int o = 16; o; o >>= 1) sc += __shfl_xor_sync(0xffffffffu, sc, o);
                ex = sc + b2v + gumbel_of((uint32_t)(row*TT + t));
                __syncwarp();
            }
            if (lane == 0) cand_pert[c] = ex;
        }
    }
    __syncthreads();

    if (refine && tid == 0) {
        int need = ki - sh_above;
        for (int c = 0; c < ncand; ++c) {
            int rank = 0;
            float pc = cand_pert[c];
            for (int c2 = 0; c2 < ncand; ++c2)
                if (cand_pert[c2] > pc) rank++;
            cand_sel[c] = (rank < need) ? 1 : 0;
        }
    }
    __syncthreads();

    // ---- g output
#pragma unroll
    for (int j = 0; j < 4; ++j) {
        int t = p0 + j;
        float p = s_cum[t];
        float a0 = s_attn[t];
        float gv;
        if (refine) {
            if (p > hiW) gv = a0;
            else if (p >= loW) {
                gv = 0.f;
                for (int c = 0; c < ncand; ++c)
                    if (cand_idx[c] == t) { gv = cand_sel[c] ? a0 : 0.f; break; }
            } else gv = 0.f;
        } else {
            gv = (p >= thr) ? a0 : 0.f;
        }
        out[BT + row*TT + t] = gv;
        s_g[t] = gv;
    }
    __syncthreads();

    // ---- TV
    float num = 0.f, den = 0.f;
    for (int t = tid; t < TT - 1; t += 1024) {
        float valid = s_attn[t] * s_attn[t+1];
        num += fabsf(s_g[t+1] - s_g[t]) * valid;
        den += valid;
    }
    for (int o = 16; o; o >>= 1) {
        num += __shfl_xor_sync(0xffffffffu, num, o);
        den += __shfl_xor_sync(0xffffffffu, den, o);
    }
    if (lane == 0) { red[wid] = num; red2[wid] = den; }
    __syncthreads();
    if (tid == 0) {
        float a = 0.f, b = 0.f;
        for (int w = 0; w < 32; w++) { a += red[w]; b += red2[w]; }
        g_tv[row] = a / fmaxf(b, 1.f);
        __threadfence();
        int n = atomicAdd(&g_done, 1);
        if (n == BB - 1) {           // last block: reduce + reset counter
            __threadfence();
            float s = 0.f;
            for (int r = 0; r < BB; r++) s += g_tv[r];
            out[2*BT] = 0.1f * (s / (float)BB);
            atomicExch(&g_done, 0);  // replay-deterministic reset
        }
    }
}

extern "C" void kernel_launch(void* const* d_in, const int* in_sizes, int n_in,
                              void* d_out, int out_size)
{
    const float* emb   = (const float*)d_in[0];
    const float* attn  = (const float*)d_in[1];
    const float* gamma = (const float*)d_in[2];
    const float* beta  = (const float*)d_in[3];
    const float* W1    = (const float*)d_in[4];
    const float* b1    = (const float*)d_in[5];
    const float* W2    = (const float*)d_in[6];
    const float* b2    = (const float*)d_in[7];
    float* out = (float*)d_out;

    cudaFuncSetAttribute(kernelA, cudaFuncAttributeMaxDynamicSharedMemorySize, SMEM_A_TOT);
    cudaFuncSetAttribute(kernelB, cudaFuncAttributeMaxDynamicSharedMemorySize, SMEM_B);

    kernelW<<<NP, 256>>>(W1, b1, W2);
    kernelA<<<BT/64, 256, SMEM_A_TOT>>>(emb, attn, gamma, beta, b2);
    kernelB<<<BB, 1024, SMEM_B>>>(attn, emb, gamma, beta, b2, out);
}

// round 16
// speedup vs baseline: 1.0345x; 1.0035x over previous
#include <cuda_runtime.h>
#include <cuda_fp16.h>
#include <cstdint>
#include <math.h>

// Problem constants
#define BB 64
#define TT 4096
#define DD 256
#define HH 341
#define BT (BB*TT)
#define NEGV (-1e9f)
#define NP 352            // hidden padded to 11*32
#define NCHUNK 11         // 32 n-cols per chunk
#define LSCALE 2048.0f
#define INV_LSCALE (1.0f/2048.0f)

__device__ float g_scores[BT];
__device__ float g_tv[BB];
__device__ int   g_done;            // zero-init; self-resetting each launch
__device__ __align__(16) __half g_w1t_hi[NP*DD];   // W1^T [h][d] fp16 hi
__device__ __align__(16) __half g_w1t_lo[NP*DD];   // fp16 residual * 2048
__device__ __align__(16) float g_w1t32[NP*DD];     // W1^T fp32 (refinement)
__device__ float g_b1p[NP];
__device__ float g_w2p[NP];

// f32-accumulator fp16 MMA
#define MMA16816F(d, a0,a1,a2,a3, b0,b1) \
    asm volatile("mma.sync.aligned.m16n8k16.row.col.f32.f16.f16.f32 " \
        "{%0,%1,%2,%3}, {%4,%5,%6,%7}, {%8,%9}, {%0,%1,%2,%3};" \
        : "+f"((d)[0]), "+f"((d)[1]), "+f"((d)[2]), "+f"((d)[3]) \
        : "r"(a0), "r"(a1), "r"(a2), "r"(a3), "r"(b0), "r"(b1))

// f16-accumulator fp16 MMA (c0 = halves r0,r1; c1 = halves r2,r3)
#define MMA16816H(c0, c1, a0,a1,a2,a3, b0,b1) \
    asm volatile("mma.sync.aligned.m16n8k16.row.col.f16.f16.f16.f16 " \
        "{%0,%1}, {%2,%3,%4,%5}, {%6,%7}, {%0,%1};" \
        : "+r"(c0), "+r"(c1) \
        : "r"(a0), "r"(a1), "r"(a2), "r"(a3), "r"(b0), "r"(b1))

#define LDSM_X4(r0,r1,r2,r3, addr) \
    asm volatile("ldmatrix.sync.aligned.m8n8.x4.shared.b16 {%0,%1,%2,%3}, [%4];" \
        : "=r"(r0), "=r"(r1), "=r"(r2), "=r"(r3) : "r"(addr))

#define CP_ASYNC16(dst, src) \
    asm volatile("cp.async.cg.shared.global [%0], [%1], 16;" :: "r"(dst), "l"(src))
#define CP_COMMIT() asm volatile("cp.async.commit_group;" ::: "memory")
#define CP_WAIT(n)  asm volatile("cp.async.wait_group %0;" :: "n"(n) : "memory")

__device__ __forceinline__ uint32_t smem_u32(const void* p) {
    uint32_t a;
    asm("{ .reg .u64 t; cvta.to.shared.u64 t, %1; cvt.u32.u64 %0, t; }" : "=r"(a) : "l"(p));
    return a;
}
__device__ __forceinline__ uint32_t packh(__half a, __half b) {
    return (uint32_t)__half_as_ushort(a) | ((uint32_t)__half_as_ushort(b) << 16);
}
__device__ __forceinline__ float2 h2f2(uint32_t v) {
    __half2 h = *reinterpret_cast<__half2*>(&v);
    return __half22float2(h);
}
__device__ __forceinline__ float gelu_w2(float v, float w2v) {
    return 0.5f*v*(1.f + erff(v*0.70710678118654752f)) * w2v;
}

// ---------------------------------------------------------------------------
// Prologue: transpose + fp16-split W1 (lo pre-scaled by 2048), pad b1/W2
// ---------------------------------------------------------------------------
__global__ void kernelW(const float* __restrict__ W1, const float* __restrict__ b1,
                        const float* __restrict__ W2)
{
    int h = blockIdx.x;       // 0..351
    int d = threadIdx.x;      // 0..255
    float w = (h < HH) ? W1[d*HH + h] : 0.f;
    __half hi = __float2half_rn(w);
    __half lo = __float2half_rn((w - __half2float(hi)) * LSCALE);
    g_w1t_hi[h*DD + d] = hi;
    g_w1t_lo[h*DD + d] = lo;
    g_w1t32[h*DD + d] = w;
    if (d == 0) {
        g_b1p[h] = (h < HH) ? b1[h] : 0.f;
        g_w2p[h] = (h < HH) ? W2[h] : 0.f;
    }
}

// ---------------------------------------------------------------------------
// Kernel A: 64-token blocks, 2 blocks/SM, fp16 3-term ldmatrix+mma GEMM
// Loop order: mma -> sync -> restage(c+1) -> epilogue (epilogue overlaps
// the cp.async flight of the next B chunk). ks loop fully unrolled.
// ---------------------------------------------------------------------------
#define RP 528
#define OFF_AHI 0
#define OFF_ALO 33792
#define OFF_B   67584
#define OFF_ATTN 101376
#define OFF_B1P 101632
#define OFF_W2P 103040
#define OFF_SC  104448
#define OFF_ANY 104704
#define SMEM_A_TOT 104768

extern __shared__ char smx[];

__device__ __forceinline__ void stage_B(int c, int tid, uint32_t sb) {
#pragma unroll
    for (int i = 0; i < 8; ++i) {
        int v = tid + i*256;
        int half_ = v >> 10;
        int r = (v >> 5) & 31;
        int u = v & 31;
        const uint4* src = (half_ ? (const uint4*)g_w1t_lo : (const uint4*)g_w1t_hi)
                         + (size_t)(c*32 + r)*32 + u;
        uint32_t dst = sb + OFF_B + half_*16896 + r*RP + u*16;
        CP_ASYNC16(dst, src);
    }
}

__global__ __launch_bounds__(256, 2)
void kernelA(const float* __restrict__ emb, const float* __restrict__ attn,
             const float* __restrict__ gamma_, const float* __restrict__ beta_,
             const float* __restrict__ b2)
{
    const int tid = threadIdx.x, lane = tid & 31, wid = tid >> 5;
    const int base = blockIdx.x * 64;
    uint32_t sb = smem_u32(smx);

    float* s_attn = (float*)(smx + OFF_ATTN);
    float* s_b1p  = (float*)(smx + OFF_B1P);
    float* s_w2p  = (float*)(smx + OFF_W2P);
    float* s_sc   = (float*)(smx + OFF_SC);
    int*   s_any  = (int*)(smx + OFF_ANY);

    if (tid == 0) *s_any = 0;
    __syncthreads();
    if (tid < 64) {
        float a = attn[base + tid];
        s_attn[tid] = a;
        s_sc[tid] = 0.f;
        if (a != 0.f) *s_any = 1;
    }
    __syncthreads();
    if (!*s_any) {
        if (tid < 64) g_scores[base + tid] = NEGV;
        return;
    }

    stage_B(0, tid, sb);
    CP_COMMIT();

    if (tid < NP) s_b1p[tid] = g_b1p[tid], s_w2p[tid] = g_w2p[tid];
    if (tid + 256 < NP) { s_b1p[tid+256] = g_b1p[tid+256]; s_w2p[tid+256] = g_w2p[tid+256]; }

    for (int it = 0; it < 8; ++it) {
        int mt = wid * 8 + it;
        const float4* e4 = (const float4*)(emb + (size_t)(base + mt) * DD);
        float4 va = e4[lane*2], vb = e4[lane*2 + 1];
        float am = s_attn[mt];
        va.x *= am; va.y *= am; va.z *= am; va.w *= am;
        vb.x *= am; vb.y *= am; vb.z *= am; vb.w *= am;
        float s  = va.x+va.y+va.z+va.w+vb.x+vb.y+vb.z+vb.w;
        float s2 = va.x*va.x+va.y*va.y+va.z*va.z+va.w*va.w
                 + vb.x*vb.x+vb.y*vb.y+vb.z*vb.z+vb.w*vb.w;
#pragma unroll
        for (int o = 16; o; o >>= 1) {
            s  += __shfl_xor_sync(0xffffffffu, s, o);
            s2 += __shfl_xor_sync(0xffffffffu, s2, o);
        }
        float mu = s * (1.f/256.f);
        float rstd = rsqrtf(s2 * (1.f/256.f) - mu*mu + 1e-5f);

        float x[8] = {va.x, va.y, va.z, va.w, vb.x, vb.y, vb.z, vb.w};
        uint32_t qh[4], ql[4];
        const int d0 = lane * 8;
#pragma unroll
        for (int p = 0; p < 4; ++p) {
            float x0 = (x[2*p]   - mu) * rstd * gamma_[d0+2*p]   + beta_[d0+2*p];
            float x1 = (x[2*p+1] - mu) * rstd * gamma_[d0+2*p+1] + beta_[d0+2*p+1];
            __half h0 = __float2half_rn(x0);
            __half h1 = __float2half_rn(x1);
            __half l0 = __float2half_rn((x0 - __half2float(h0)) * LSCALE);
            __half l1 = __float2half_rn((x1 - __half2float(h1)) * LSCALE);
            qh[p] = packh(h0, h1);
            ql[p] = packh(l0, l1);
        }
        uint32_t off = mt * RP + lane * 16;
        *(uint4*)(smx + OFF_AHI + off) = make_uint4(qh[0],qh[1],qh[2],qh[3]);
        *(uint4*)(smx + OFF_ALO + off) = make_uint4(ql[0],ql[1],ql[2],ql[3]);
    }

    const int wm = wid & 3;
    const int wn = wid >> 2;
    const int m0 = wm * 16;
    const int g = lane >> 2, q = lane & 3;
    const int lrow = lane & 15;
    const int lcol = (lane >> 4) * 16;

    const uint32_t aAddrHi = sb + OFF_AHI + (m0 + lrow) * RP + lcol;
    const uint32_t aAddrLo = sb + OFF_ALO + (m0 + lrow) * RP + lcol;
    const uint32_t bHi = sb + OFF_B + (wn*16 + lrow) * RP + lcol;
    const uint32_t bLo = bHi + 16896;

    float part0 = 0.f, part1 = 0.f;

    for (int c = 0; c < NCHUNK; ++c) {
        CP_WAIT(0);
        __syncthreads();    // B chunk c visible to all

        float hA0[4] = {0.f,0.f,0.f,0.f};
        float hA1[4] = {0.f,0.f,0.f,0.f};
        uint32_t xA0a = 0u, xA0b = 0u;
        uint32_t xB0a = 0u, xB0b = 0u;
        uint32_t xA1a = 0u, xA1b = 0u;
        uint32_t xB1a = 0u, xB1b = 0u;

#pragma unroll 16
        for (int ks = 0; ks < 16; ++ks) {
            const int kb = ks * 32;
            uint32_t ah0,ah1,ah2,ah3, al0,al1,al2,al3;
            uint32_t bh0,bh1,bh2,bh3, bl0,bl1,bl2,bl3;
            LDSM_X4(ah0,ah1,ah2,ah3, aAddrHi + kb);
            LDSM_X4(al0,al1,al2,al3, aAddrLo + kb);
            LDSM_X4(bh0,bh1,bh2,bh3, bHi + kb);
            LDSM_X4(bl0,bl1,bl2,bl3, bLo + kb);
            MMA16816F(hA0, ah0,ah1,ah2,ah3, bh0,bh2);
            MMA16816H(xA0a,xA0b, ah0,ah1,ah2,ah3, bl0,bl2);
            MMA16816H(xB0a,xB0b, al0,al1,al2,al3, bh0,bh2);
            MMA16816F(hA1, ah0,ah1,ah2,ah3, bh1,bh3);
            MMA16816H(xA1a,xA1b, ah0,ah1,ah2,ah3, bl1,bl3);
            MMA16816H(xB1a,xB1b, al0,al1,al2,al3, bh1,bh3);
        }

        __syncthreads();    // all warps done reading buf before restage
        if (c + 1 < NCHUNK) { stage_B(c+1, tid, sb); CP_COMMIT(); }

        // epilogue overlaps the cp.async flight of chunk c+1
        {
            float2 pA0 = h2f2(xA0a), pA0b = h2f2(xA0b);
            float2 pB0 = h2f2(xB0a), pB0b = h2f2(xB0b);
            float2 pA1 = h2f2(xA1a), pA1b = h2f2(xA1b);
            float2 pB1 = h2f2(xB1a), pB1b = h2f2(xB1b);
            float acc0[4], acc1[4];
            acc0[0] = hA0[0] + (pA0.x  + pB0.x ) * INV_LSCALE;
            acc0[1] = hA0[1] + (pA0.y  + pB0.y ) * INV_LSCALE;
            acc0[2] = hA0[2] + (pA0b.x + pB0b.x) * INV_LSCALE;
            acc0[3] = hA0[3] + (pA0b.y + pB0b.y) * INV_LSCALE;
            acc1[0] = hA1[0] + (pA1.x  + pB1.x ) * INV_LSCALE;
            acc1[1] = hA1[1] + (pA1.y  + pB1.y ) * INV_LSCALE;
            acc1[2] = hA1[2] + (pA1b.x + pB1b.x) * INV_LSCALE;
            acc1[3] = hA1[3] + (pA1b.y + pB1b.y) * INV_LSCALE;

            int hb = c*32 + wn*16 + 2*q;
            float b1a = s_b1p[hb],   w2a = s_w2p[hb];
            float b1b = s_b1p[hb+1], w2b = s_w2p[hb+1];
            part0 += gelu_w2(acc0[0] + b1a, w2a) + gelu_w2(acc0[1] + b1b, w2b);
            part1 += gelu_w2(acc0[2] + b1a, w2a) + gelu_w2(acc0[3] + b1b, w2b);
            int hc = hb + 8;
            float b1c = s_b1p[hc],   w2c = s_w2p[hc];
            float b1d = s_b1p[hc+1], w2d = s_w2p[hc+1];
            part0 += gelu_w2(acc1[0] + b1c, w2c) + gelu_w2(acc1[1] + b1d, w2d);
            part1 += gelu_w2(acc1[2] + b1c, w2c) + gelu_w2(acc1[3] + b1d, w2d);
        }
    }

    part0 += __shfl_xor_sync(0xffffffffu, part0, 1);
    part0 += __shfl_xor_sync(0xffffffffu, part0, 2);
    part1 += __shfl_xor_sync(0xffffffffu, part1, 1);
    part1 += __shfl_xor_sync(0xffffffffu, part1, 2);
    if (q == 0) {
        atomicAdd(&s_sc[m0 + g], part0);
        atomicAdd(&s_sc[m0 + g + 8], part1);
    }
    __syncthreads();
    if (tid < 64) {
        float sc = s_sc[tid] + b2[0];
        if (s_attn[tid] == 0.f) sc = NEGV;
        g_scores[base + tid] = sc;
    }
}

// ---------------------------------------------------------------------------
// Threefry-2x32-20, JAX partitionable: ctr=(0,i), draw = out0 ^ out1
// ---------------------------------------------------------------------------
__device__ __forceinline__ uint32_t rotl32(uint32_t x, int r) { return (x << r) | (x >> (32 - r)); }
__device__ __forceinline__ void tf_r4(uint32_t& x0, uint32_t& x1, int a, int b, int c, int d) {
    x0 += x1; x1 = rotl32(x1, a); x1 ^= x0;
    x0 += x1; x1 = rotl32(x1, b); x1 ^= x0;
    x0 += x1; x1 = rotl32(x1, c); x1 ^= x0;
    x0 += x1; x1 = rotl32(x1, d); x1 ^= x0;
}
__device__ __forceinline__ uint32_t jax_bits(uint32_t i) {
    const uint32_t k0 = 0u, k1 = 42u;
    const uint32_t k2 = k0 ^ k1 ^ 0x1BD11BDAu;
    uint32_t x0 = 0u + k0;
    uint32_t x1 = i  + k1;
    tf_r4(x0, x1, 13, 15, 26, 6);   x0 += k1; x1 += k2 + 1u;
    tf_r4(x0, x1, 17, 29, 16, 24);  x0 += k2; x1 += k0 + 2u;
    tf_r4(x0, x1, 13, 15, 26, 6);   x0 += k0; x1 += k1 + 3u;
    tf_r4(x0, x1, 17, 29, 16, 24);  x0 += k1; x1 += k2 + 4u;
    tf_r4(x0, x1, 13, 15, 26, 6);   x0 += k2; x1 += k0 + 5u;
    return x0 ^ x1;
}
__device__ __forceinline__ float gumbel_of(uint32_t lin) {
    uint32_t bits = jax_bits(lin);
    float u = __uint_as_float((bits >> 9) | 0x3f800000u) - 1.0f;
    u = fmaxf(u, 0.f);
    return -logf(-logf(u + 1e-6f) + 1e-6f);
}

// ---------------------------------------------------------------------------
// Kernel B: entmax1.5 bisection + radix-select top-k + exact refinement + TV
// Last block also reduces g_tv -> reg (kernelC folded in).
// ---------------------------------------------------------------------------
#define EPS_W 1.5e-4f
#define MAXC 64
#define SMEM_B ((4*4096 + 32*256)*4)

__global__ __launch_bounds__(1024, 1)
void kernelB(const float* __restrict__ attn, const float* __restrict__ emb,
             const float* __restrict__ gamma_, const float* __restrict__ beta_,
             const float* __restrict__ b2, float* __restrict__ out)
{
    extern __shared__ float sm[];
    float* s_scores = sm;             // 4096
    float* s_attn   = sm + 4096;      // 4096
    float* s_cum    = sm + 8192;      // 4096 (pert)
    float* s_g      = sm + 12288;     // 4096 (g staging for TV)
    float* s_xn     = sm + 16384;     // [32 warps][256]
    __shared__ float red[32], red2[32], red3[32];
    __shared__ float sh_mx, sh_teff, sh_tau, sh_thr, sh_S;
    __shared__ int sh_above, sh_ncand;
    __shared__ int hist[256];
    __shared__ uint32_t sh_prefix;
    __shared__ int sh_remain;
    __shared__ int cand_idx[MAXC];
    __shared__ float cand_pert[MAXC];
    __shared__ int cand_sel[MAXC];

    const int row = blockIdx.x;
    const int tid = threadIdx.x;
    const int lane = tid & 31, wid = tid >> 5;
    const int p0 = tid * 4;

    // ---- load + t_eff + row max
    float tf_ = 0.f, mx = -3.402823466e38f;
    for (int t = tid; t < TT; t += 1024) {
        float s = g_scores[row*TT + t];
        float a = attn[row*TT + t];
        s_scores[t] = s; s_attn[t] = a;
        tf_ += a; mx = fmaxf(mx, s);
    }
    for (int o = 16; o; o >>= 1) {
        tf_ += __shfl_xor_sync(0xffffffffu, tf_, o);
        mx = fmaxf(mx, __shfl_xor_sync(0xffffffffu, mx, o));
    }
    if (lane == 0) { red[wid] = tf_; red2[wid] = mx; }
    __syncthreads();
    if (tid == 0) {
        float a = 0.f, b = -3.402823466e38f;
        for (int w = 0; w < 32; w++) { a += red[w]; b = fmaxf(b, red2[w]); }
        sh_teff = a; sh_mx = b;
        sh_above = 0; sh_ncand = 0;
    }
    __syncthreads();
    mx = sh_mx;

    // ---- entmax tau via bisection on f(tau) = sum max(x-tau,0)^2 (dec.)
    float xr[4];
#pragma unroll
    for (int j = 0; j < 4; ++j) xr[j] = (s_scores[p0+j] - mx) * 0.5f;

    float lo = -1.0f, hi = 0.0f;
    for (int it = 0; it < 28; ++it) {
        float tau = 0.5f*(lo + hi);
        float ssum = 0.f;
#pragma unroll
        for (int j = 0; j < 4; ++j) {
            float d = fmaxf(xr[j] - tau, 0.f);
            ssum += d*d;
        }
        for (int o = 16; o; o >>= 1) ssum += __shfl_xor_sync(0xffffffffu, ssum, o);
        if (lane == 0) red[wid] = ssum;
        __syncthreads();
        if (tid == 0) {
            float a = 0.f;
            for (int w = 0; w < 32; w++) a += red[w];
            sh_S = a;
        }
        __syncthreads();
        if (sh_S > 1.f) lo = tau; else hi = tau;
    }
    // support stats over {x > tau_b}, then exact tau* from the support set
    {
        float taub = 0.5f*(lo + hi);
        float c = 0.f, S1 = 0.f, S2 = 0.f;
#pragma unroll
        for (int j = 0; j < 4; ++j) {
            if (xr[j] > taub) { c += 1.f; S1 += xr[j]; S2 += xr[j]*xr[j]; }
        }
        for (int o = 16; o; o >>= 1) {
            c  += __shfl_xor_sync(0xffffffffu, c, o);
            S1 += __shfl_xor_sync(0xffffffffu, S1, o);
            S2 += __shfl_xor_sync(0xffffffffu, S2, o);
        }
        if (lane == 0) { red[wid] = c; red2[wid] = S1; red3[wid] = S2; }
        __syncthreads();
        if (tid == 0) {
            float cc = 0.f, a1 = 0.f, a2 = 0.f;
            for (int w = 0; w < 32; w++) { cc += red[w]; a1 += red2[w]; a2 += red3[w]; }
            float rho = fmaxf(cc, 1.f);
            float mean = a1 / rho;
            float msq  = a2 / rho;
            float ssv  = rho * (msq - mean*mean);
            float delta = (1.f - ssv) / rho;
            sh_tau = mean - sqrtf(fmaxf(delta, 0.f));
        }
        __syncthreads();
    }
    const float taustar = sh_tau;

    // ---- z output
#pragma unroll
    for (int j = 0; j < 4; ++j) {
        float dd = fmaxf(xr[j] - taustar, 0.f);
        out[row*TT + p0 + j] = dd*dd*s_attn[p0+j];
    }

    // ---- gumbel-perturbed scores (+ radix keys in registers)
    uint32_t ur[4];
#pragma unroll
    for (int j = 0; j < 4; ++j) {
        int t = p0 + j;
        float gum = gumbel_of((uint32_t)(row*TT + t));
        float pert = s_scores[t] * s_attn[t] + gum;
        s_cum[t] = pert;
        uint32_t b = __float_as_uint(pert);
        ur[j] = (pert != pert) ? 0u
              : (b ^ ((b >> 31) ? 0xFFFFFFFFu : 0x80000000u));
    }

    const float teff = sh_teff;
    float kf = rintf(0.3f * teff);
    kf = fminf(fmaxf(kf, 1.f), fmaxf(teff, 1.f));
    const int ki = (int)kf;

    // ---- radix select: exact ki-th largest pert (MSB-first, 8 bits/round)
    if (tid == 0) { sh_prefix = 0u; sh_remain = ki; }
    __syncthreads();
    for (int sha = 24; sha >= 0; sha -= 8) {
        if (tid < 256) hist[tid] = 0;
        __syncthreads();
        uint32_t pref = sh_prefix;
#pragma unroll
        for (int j = 0; j < 4; ++j) {
            uint32_t u = ur[j];
            bool match = (sha == 24) || ((u >> (sha + 8)) == pref);
            if (match) atomicAdd(&hist[(u >> sha) & 255], 1);
        }
        __syncthreads();
        if (wid == 0) {
            int b0 = 255 - lane*8;
            int cnt[8];
            int s = 0;
#pragma unroll
            for (int i = 0; i < 8; i++) { cnt[i] = hist[b0 - i]; s += cnt[i]; }
            int pre = s;
            for (int o = 1; o < 32; o <<= 1) {
                int n = __shfl_up_sync(0xffffffffu, pre, o);
                if (lane >= o) pre += n;
            }
            int excl = pre - s;
            int rem = sh_remain;
            if (excl < rem && rem <= excl + s) {
                int acc = excl;
#pragma unroll
                for (int i = 0; i < 8; i++) {
                    if (acc + cnt[i] >= rem) {
                        uint32_t oldp = sh_prefix;
                        sh_prefix = (oldp << 8) | (uint32_t)(b0 - i);
                        sh_remain = rem - acc;
                        break;
                    }
                    acc += cnt[i];
                }
            }
        }
        __syncthreads();
    }
    if (tid == 0) {
        uint32_t su = sh_prefix;
        uint32_t tb = (su & 0x80000000u) ? (su ^ 0x80000000u) : ~su;
        sh_thr = __uint_as_float(tb);
    }
    __syncthreads();
    const float thr = sh_thr;
    const float hiW = thr + EPS_W, loW = thr - EPS_W;

    // ---- classification counts + candidate gather
    {
        int my_above = 0;
#pragma unroll
        for (int j = 0; j < 4; ++j) {
            int t = p0 + j;
            float p = s_cum[t];
            if (p > hiW) my_above++;
            else if (p >= loW) {
                int pos = atomicAdd(&sh_ncand, 1);
                if (pos < MAXC) cand_idx[pos] = t;
            }
        }
        for (int o = 16; o; o >>= 1) my_above += __shfl_xor_sync(0xffffffffu, my_above, o);
        if (lane == 0) atomicAdd(&sh_above, my_above);
    }
    __syncthreads();
    const int ncand = sh_ncand;
    const bool refine = (ncand <= MAXC);

    // ---- exact recompute of candidate perts (warp per candidate)
    if (refine) {
        const float b2v = b2[0];
        for (int c = wid; c < ncand; c += 32) {
            int t = cand_idx[c];
            float ex;
            if (s_attn[t] == 0.f) {
                ex = s_cum[t];
            } else {
                const float4* e4 = (const float4*)(emb + ((size_t)row*TT + t)*DD);
                float4 va = e4[lane*2], vb = e4[lane*2+1];
                float s  = va.x+va.y+va.z+va.w+vb.x+vb.y+vb.z+vb.w;
                float s2 = va.x*va.x+va.y*va.y+va.z*va.z+va.w*va.w
                         + vb.x*vb.x+vb.y*vb.y+vb.z*vb.z+vb.w*vb.w;
#pragma unroll
                for (int o = 16; o; o >>= 1) {
                    s  += __shfl_xor_sync(0xffffffffu, s, o);
                    s2 += __shfl_xor_sync(0xffffffffu, s2, o);
                }
                float mu = s * (1.f/256.f);
                float rstd = rsqrtf(s2 * (1.f/256.f) - mu*mu + 1e-5f);
                float xv[8] = {va.x,va.y,va.z,va.w,vb.x,vb.y,vb.z,vb.w};
                float* xw = s_xn + wid*256 + lane*8;
#pragma unroll
                for (int p = 0; p < 8; ++p) {
                    int d = lane*8 + p;
                    xw[p] = (xv[p] - mu) * rstd * gamma_[d] + beta_[d];
                }
                __syncwarp();
                float sc = 0.f;
                for (int h = lane; h < HH; h += 32) {
                    const float4* wr = (const float4*)(g_w1t32 + (size_t)h*DD);
                    const float4* xq = (const float4*)(s_xn + wid*256);
                    float dot = 0.f;
#pragma unroll 8
                    for (int u = 0; u < 64; ++u) {
                        float4 a = wr[u], bq = xq[u];
                        dot += a.x*bq.x + a.y*bq.y + a.z*bq.z + a.w*bq.w;
                    }
                    float v = dot + g_b1p[h];
                    sc += gelu_w2(v, g_w2p[h]);
                }
#pragma unroll
                for (int o = 16; o; o >>= 1) sc += __shfl_xor_sync(0xffffffffu, sc, o);
                ex = sc + b2v + gumbel_of((uint32_t)(row*TT + t));
                __syncwarp();
            }
            if (lane == 0) cand_pert[c] = ex;
        }
    }
    __syncthreads();

    if (refine && tid == 0) {
        int need = ki - sh_above;
        for (int c = 0; c < ncand; ++c) {
            int rank = 0;
            float pc = cand_pert[c];
            for (int c2 = 0; c2 < ncand; ++c2)
                if (cand_pert[c2] > pc) rank++;
            cand_sel[c] = (rank < need) ? 1 : 0;
        }
    }
    __syncthreads();

    // ---- g output
#pragma unroll
    for (int j = 0; j < 4; ++j) {
        int t = p0 + j;
        float p = s_cum[t];
        float a0 = s_attn[t];
        float gv;
        if (refine) {
            if (p > hiW) gv = a0;
            else if (p >= loW) {
                gv = 0.f;
                for (int c = 0; c < ncand; ++c)
                    if (cand_idx[c] == t) { gv = cand_sel[c] ? a0 : 0.f; break; }
            } else gv = 0.f;
        } else {
            gv = (p >= thr) ? a0 : 0.f;
        }
        out[BT + row*TT + t] = gv;
        s_g[t] = gv;
    }
    __syncthreads();

    // ---- TV
    float num = 0.f, den = 0.f;
    for (int t = tid; t < TT - 1; t += 1024) {
        float valid = s_attn[t] * s_attn[t+1];
        num += fabsf(s_g[t+1] - s_g[t]) * valid;
        den += valid;
    }
    for (int o = 16; o; o >>= 1) {
        num += __shfl_xor_sync(0xffffffffu, num, o);
        den += __shfl_xor_sync(0xffffffffu, den, o);
    }
    if (lane == 0) { red[wid] = num; red2[wid] = den; }
    __syncthreads();
    if (tid == 0) {
        float a = 0.f, b = 0.f;
        for (int w = 0; w < 32; w++) { a += red[w]; b += red2[w]; }
        g_tv[row] = a / fmaxf(b, 1.f);
        __threadfence();
        int n = atomicAdd(&g_done, 1);
        if (n == BB - 1) {           // last block: reduce + reset counter
            __threadfence();
            float s = 0.f;
            for (int r = 0; r < BB; r++) s += g_tv[r];
            out[2*BT] = 0.1f * (s / (float)BB);
            atomicExch(&g_done, 0);  // replay-deterministic reset
        }
    }
}

extern "C" void kernel_launch(void* const* d_in, const int* in_sizes, int n_in,
                              void* d_out, int out_size)
{
    const float* emb   = (const float*)d_in[0];
    const float* attn  = (const float*)d_in[1];
    const float* gamma = (const float*)d_in[2];
    const float* beta  = (const float*)d_in[3];
    const float* W1    = (const float*)d_in[4];
    const float* b1    = (const float*)d_in[5];
    const float* W2    = (const float*)d_in[6];
    const float* b2    = (const float*)d_in[7];
    float* out = (float*)d_out;

    cudaFuncSetAttribute(kernelA, cudaFuncAttributeMaxDynamicSharedMemorySize, SMEM_A_TOT);
    cudaFuncSetAttribute(kernelB, cudaFuncAttributeMaxDynamicSharedMemorySize, SMEM_B);

    kernelW<<<NP, 256>>>(W1, b1, W2);
    kernelA<<<BT/64, 256, SMEM_A_TOT>>>(emb, attn, gamma, beta, b2);
    kernelB<<<BB, 1024, SMEM_B>>>(attn, emb, gamma, beta, b2, out);
}

// round 17
// speedup vs baseline: 1.0699x; 1.0342x over previous
#include <cuda_runtime.h>
#include <cuda_fp16.h>
#include <cstdint>
#include <math.h>

// Problem constants
#define BB 64
#define TT 4096
#define DD 256
#define HH 341
#define BT (BB*TT)
#define NEGV (-1e9f)
#define NP 352            // hidden padded to 11*32
#define NCHUNK 11         // 32 n-cols per chunk
#define LSCALE 2048.0f
#define INV_LSCALE (1.0f/2048.0f)

__device__ float g_scores[BT];
__device__ float g_tv[BB];
__device__ int   g_done;            // zero-init; self-resetting each launch
__device__ __align__(16) __half g_w1t_hi[NP*DD];   // W1^T [h][d] fp16 hi
__device__ __align__(16) __half g_w1t_lo[NP*DD];   // fp16 residual * 2048
__device__ __align__(16) float g_w1t32[NP*DD];     // W1^T fp32 (refinement)
__device__ float g_b1p[NP];
__device__ float g_w2p[NP];

// f32-accumulator fp16 MMA
#define MMA16816F(d, a0,a1,a2,a3, b0,b1) \
    asm volatile("mma.sync.aligned.m16n8k16.row.col.f32.f16.f16.f32 " \
        "{%0,%1,%2,%3}, {%4,%5,%6,%7}, {%8,%9}, {%0,%1,%2,%3};" \
        : "+f"((d)[0]), "+f"((d)[1]), "+f"((d)[2]), "+f"((d)[3]) \
        : "r"(a0), "r"(a1), "r"(a2), "r"(a3), "r"(b0), "r"(b1))

// f16-accumulator fp16 MMA (c0 = halves r0,r1; c1 = halves r2,r3)
#define MMA16816H(c0, c1, a0,a1,a2,a3, b0,b1) \
    asm volatile("mma.sync.aligned.m16n8k16.row.col.f16.f16.f16.f16 " \
        "{%0,%1}, {%2,%3,%4,%5}, {%6,%7}, {%0,%1};" \
        : "+r"(c0), "+r"(c1) \
        : "r"(a0), "r"(a1), "r"(a2), "r"(a3), "r"(b0), "r"(b1))

#define LDSM_X4(r0,r1,r2,r3, addr) \
    asm volatile("ldmatrix.sync.aligned.m8n8.x4.shared.b16 {%0,%1,%2,%3}, [%4];" \
        : "=r"(r0), "=r"(r1), "=r"(r2), "=r"(r3) : "r"(addr))

#define CP_ASYNC16(dst, src) \
    asm volatile("cp.async.cg.shared.global [%0], [%1], 16;" :: "r"(dst), "l"(src))
#define CP_COMMIT() asm volatile("cp.async.commit_group;" ::: "memory")
#define CP_WAIT(n)  asm volatile("cp.async.wait_group %0;" :: "n"(n) : "memory")
#define BAR_SYNC(id, n) asm volatile("bar.sync %0, %1;" :: "r"(id), "r"(n) : "memory")

__device__ __forceinline__ uint32_t smem_u32(const void* p) {
    uint32_t a;
    asm("{ .reg .u64 t; cvta.to.shared.u64 t, %1; cvt.u32.u64 %0, t; }" : "=r"(a) : "l"(p));
    return a;
}
__device__ __forceinline__ uint32_t packh(__half a, __half b) {
    return (uint32_t)__half_as_ushort(a) | ((uint32_t)__half_as_ushort(b) << 16);
}
__device__ __forceinline__ float2 h2f2(uint32_t v) {
    __half2 h = *reinterpret_cast<__half2*>(&v);
    return __half22float2(h);
}
__device__ __forceinline__ float gelu_w2(float v, float w2v) {
    return 0.5f*v*(1.f + erff(v*0.70710678118654752f)) * w2v;
}

// ---------------------------------------------------------------------------
// Prologue: transpose + fp16-split W1 (lo pre-scaled by 2048), pad b1/W2
// ---------------------------------------------------------------------------
__global__ void kernelW(const float* __restrict__ W1, const float* __restrict__ b1,
                        const float* __restrict__ W2)
{
    int h = blockIdx.x;       // 0..351
    int d = threadIdx.x;      // 0..255
    float w = (h < HH) ? W1[d*HH + h] : 0.f;
    __half hi = __float2half_rn(w);
    __half lo = __float2half_rn((w - __half2float(hi)) * LSCALE);
    g_w1t_hi[h*DD + d] = hi;
    g_w1t_lo[h*DD + d] = lo;
    g_w1t32[h*DD + d] = w;
    if (d == 0) {
        g_b1p[h] = (h < HH) ? b1[h] : 0.f;
        g_w2p[h] = (h < HH) ? W2[h] : 0.f;
    }
}

// ---------------------------------------------------------------------------
// Kernel A: 64-token blocks, 2 blocks/SM, fp16 3-term ldmatrix+mma GEMM.
// Per-chunk barriers are SPLIT by n-half (named bar 1/2, 128 threads each):
// each half stages and reads its own disjoint 16 B rows, so the two halves
// (and the 2 co-resident blocks) form 4 independent barrier domains per SM.
// A is immutable after the build phase (one full __syncthreads covers it).
// ---------------------------------------------------------------------------
#define RP 528
#define OFF_AHI 0
#define OFF_ALO 33792
#define OFF_B   67584
#define OFF_ATTN 101376
#define OFF_B1P 101632
#define OFF_W2P 103040
#define OFF_SC  104448
#define OFF_ANY 104704
#define SMEM_A_TOT 104768

extern __shared__ char smx[];

// stage this n-half's 16 B rows (hi+lo) of chunk c; 128 threads, 8 vecs each
__device__ __forceinline__ void stage_B_half(int c, int grp, int tid128, uint32_t sb) {
#pragma unroll
    for (int i = 0; i < 8; ++i) {
        int v = tid128 + i*128;           // 0..1023
        int half_ = v >> 9;               // 0=hi, 1=lo
        int r = (v >> 5) & 15;            // row within half
        int u = v & 31;
        const uint4* src = (half_ ? (const uint4*)g_w1t_lo : (const uint4*)g_w1t_hi)
                         + (size_t)(c*32 + grp*16 + r)*32 + u;
        uint32_t dst = sb + OFF_B + half_*16896 + (grp*16 + r)*RP + u*16;
        CP_ASYNC16(dst, src);
    }
}

__global__ __launch_bounds__(256, 2)
void kernelA(const float* __restrict__ emb, const float* __restrict__ attn,
             const float* __restrict__ gamma_, const float* __restrict__ beta_,
             const float* __restrict__ b2)
{
    const int tid = threadIdx.x, lane = tid & 31, wid = tid >> 5;
    const int base = blockIdx.x * 64;
    uint32_t sb = smem_u32(smx);

    float* s_attn = (float*)(smx + OFF_ATTN);
    float* s_b1p  = (float*)(smx + OFF_B1P);
    float* s_w2p  = (float*)(smx + OFF_W2P);
    float* s_sc   = (float*)(smx + OFF_SC);
    int*   s_any  = (int*)(smx + OFF_ANY);

    const int wn = wid >> 2;          // n-half group (0/1)
    const int tid128 = tid & 127;     // thread index within group
    const int barid = wn + 1;         // named barrier 1 or 2

    if (tid == 0) *s_any = 0;
    __syncthreads();
    if (tid < 64) {
        float a = attn[base + tid];
        s_attn[tid] = a;
        s_sc[tid] = 0.f;
        if (a != 0.f) *s_any = 1;
    }
    __syncthreads();
    if (!*s_any) {
        if (tid < 64) g_scores[base + tid] = NEGV;
        return;
    }

    // each half prefetches its own 16 rows of B chunk 0
    stage_B_half(0, wn, tid128, sb);
    CP_COMMIT();

    if (tid < NP) s_b1p[tid] = g_b1p[tid], s_w2p[tid] = g_w2p[tid];
    if (tid + 256 < NP) { s_b1p[tid+256] = g_b1p[tid+256]; s_w2p[tid+256] = g_w2p[tid+256]; }

    for (int it = 0; it < 8; ++it) {
        int mt = wid * 8 + it;
        const float4* e4 = (const float4*)(emb + (size_t)(base + mt) * DD);
        float4 va = e4[lane*2], vb = e4[lane*2 + 1];
        float am = s_attn[mt];
        va.x *= am; va.y *= am; va.z *= am; va.w *= am;
        vb.x *= am; vb.y *= am; vb.z *= am; vb.w *= am;
        float s  = va.x+va.y+va.z+va.w+vb.x+vb.y+vb.z+vb.w;
        float s2 = va.x*va.x+va.y*va.y+va.z*va.z+va.w*va.w
                 + vb.x*vb.x+vb.y*vb.y+vb.z*vb.z+vb.w*vb.w;
#pragma unroll
        for (int o = 16; o; o >>= 1) {
            s  += __shfl_xor_sync(0xffffffffu, s, o);
            s2 += __shfl_xor_sync(0xffffffffu, s2, o);
        }
        float mu = s * (1.f/256.f);
        float rstd = rsqrtf(s2 * (1.f/256.f) - mu*mu + 1e-5f);

        float x[8] = {va.x, va.y, va.z, va.w, vb.x, vb.y, vb.z, vb.w};
        uint32_t qh[4], ql[4];
        const int d0 = lane * 8;
#pragma unroll
        for (int p = 0; p < 4; ++p) {
            float x0 = (x[2*p]   - mu) * rstd * gamma_[d0+2*p]   + beta_[d0+2*p];
            float x1 = (x[2*p+1] - mu) * rstd * gamma_[d0+2*p+1] + beta_[d0+2*p+1];
            __half h0 = __float2half_rn(x0);
            __half h1 = __float2half_rn(x1);
            __half l0 = __float2half_rn((x0 - __half2float(h0)) * LSCALE);
            __half l1 = __float2half_rn((x1 - __half2float(h1)) * LSCALE);
            qh[p] = packh(h0, h1);
            ql[p] = packh(l0, l1);
        }
        uint32_t off = mt * RP + lane * 16;
        *(uint4*)(smx + OFF_AHI + off) = make_uint4(qh[0],qh[1],qh[2],qh[3]);
        *(uint4*)(smx + OFF_ALO + off) = make_uint4(ql[0],ql[1],ql[2],ql[3]);
    }
    __syncthreads();    // A tiles visible to ALL warps (A immutable after this)

    const int wm = wid & 3;
    const int m0 = wm * 16;
    const int g = lane >> 2, q = lane & 3;
    const int lrow = lane & 15;
    const int lcol = (lane >> 4) * 16;

    const uint32_t aAddrHi = sb + OFF_AHI + (m0 + lrow) * RP + lcol;
    const uint32_t aAddrLo = sb + OFF_ALO + (m0 + lrow) * RP + lcol;
    const uint32_t bHi = sb + OFF_B + (wn*16 + lrow) * RP + lcol;
    const uint32_t bLo = bHi + 16896;

    float part0 = 0.f, part1 = 0.f;

    for (int c = 0; c < NCHUNK; ++c) {
        CP_WAIT(0);
        BAR_SYNC(barid, 128);   // this half's B chunk c visible to its 4 warps

        float hA0[4] = {0.f,0.f,0.f,0.f};
        float hA1[4] = {0.f,0.f,0.f,0.f};
        uint32_t xA0a = 0u, xA0b = 0u;
        uint32_t xB0a = 0u, xB0b = 0u;
        uint32_t xA1a = 0u, xA1b = 0u;
        uint32_t xB1a = 0u, xB1b = 0u;

#pragma unroll 16
        for (int ks = 0; ks < 16; ++ks) {
            const int kb = ks * 32;
            uint32_t ah0,ah1,ah2,ah3, al0,al1,al2,al3;
            uint32_t bh0,bh1,bh2,bh3, bl0,bl1,bl2,bl3;
            LDSM_X4(ah0,ah1,ah2,ah3, aAddrHi + kb);
            LDSM_X4(al0,al1,al2,al3, aAddrLo + kb);
            LDSM_X4(bh0,bh1,bh2,bh3, bHi + kb);
            LDSM_X4(bl0,bl1,bl2,bl3, bLo + kb);
            MMA16816F(hA0, ah0,ah1,ah2,ah3, bh0,bh2);
            MMA16816H(xA0a,xA0b, ah0,ah1,ah2,ah3, bl0,bl2);
            MMA16816H(xB0a,xB0b, al0,al1,al2,al3, bh0,bh2);
            MMA16816F(hA1, ah0,ah1,ah2,ah3, bh1,bh3);
            MMA16816H(xA1a,xA1b, ah0,ah1,ah2,ah3, bl1,bl3);
            MMA16816H(xB1a,xB1b, al0,al1,al2,al3, bh1,bh3);
        }

        BAR_SYNC(barid, 128);   // half's 4 warps done reading before restage
        if (c + 1 < NCHUNK) { stage_B_half(c+1, wn, tid128, sb); CP_COMMIT(); }

        // epilogue overlaps the cp.async flight of chunk c+1
        {
            float2 pA0 = h2f2(xA0a), pA0b = h2f2(xA0b);
            float2 pB0 = h2f2(xB0a), pB0b = h2f2(xB0b);
            float2 pA1 = h2f2(xA1a), pA1b = h2f2(xA1b);
            float2 pB1 = h2f2(xB1a), pB1b = h2f2(xB1b);
            float acc0[4], acc1[4];
            acc0[0] = hA0[0] + (pA0.x  + pB0.x ) * INV_LSCALE;
            acc0[1] = hA0[1] + (pA0.y  + pB0.y ) * INV_LSCALE;
            acc0[2] = hA0[2] + (pA0b.x + pB0b.x) * INV_LSCALE;
            acc0[3] = hA0[3] + (pA0b.y + pB0b.y) * INV_LSCALE;
            acc1[0] = hA1[0] + (pA1.x  + pB1.x ) * INV_LSCALE;
            acc1[1] = hA1[1] + (pA1.y  + pB1.y ) * INV_LSCALE;
            acc1[2] = hA1[2] + (pA1b.x + pB1b.x) * INV_LSCALE;
            acc1[3] = hA1[3] + (pA1b.y + pB1b.y) * INV_LSCALE;

            int hb = c*32 + wn*16 + 2*q;
            float b1a = s_b1p[hb],   w2a = s_w2p[hb];
            float b1b = s_b1p[hb+1], w2b = s_w2p[hb+1];
            part0 += gelu_w2(acc0[0] + b1a, w2a) + gelu_w2(acc0[1] + b1b, w2b);
            part1 += gelu_w2(acc0[2] + b1a, w2a) + gelu_w2(acc0[3] + b1b, w2b);
            int hc = hb + 8;
            float b1c = s_b1p[hc],   w2c = s_w2p[hc];
            float b1d = s_b1p[hc+1], w2d = s_w2p[hc+1];
            part0 += gelu_w2(acc1[0] + b1c, w2c) + gelu_w2(acc1[1] + b1d, w2d);
            part1 += gelu_w2(acc1[2] + b1c, w2c) + gelu_w2(acc1[3] + b1d, w2d);
        }
    }

    part0 += __shfl_xor_sync(0xffffffffu, part0, 1);
    part0 += __shfl_xor_sync(0xffffffffu, part0, 2);
    part1 += __shfl_xor_sync(0xffffffffu, part1, 1);
    part1 += __shfl_xor_sync(0xffffffffu, part1, 2);
    if (q == 0) {
        atomicAdd(&s_sc[m0 + g], part0);
        atomicAdd(&s_sc[m0 + g + 8], part1);
    }
    __syncthreads();
    if (tid < 64) {
        float sc = s_sc[tid] + b2[0];
        if (s_attn[tid] == 0.f) sc = NEGV;
        g_scores[base + tid] = sc;
    }
}

// ---------------------------------------------------------------------------
// Threefry-2x32-20, JAX partitionable: ctr=(0,i), draw = out0 ^ out1
// ---------------------------------------------------------------------------
__device__ __forceinline__ uint32_t rotl32(uint32_t x, int r) { return (x << r) | (x >> (32 - r)); }
__device__ __forceinline__ void tf_r4(uint32_t& x0, uint32_t& x1, int a, int b, int c, int d) {
    x0 += x1; x1 = rotl32(x1, a); x1 ^= x0;
    x0 += x1; x1 = rotl32(x1, b); x1 ^= x0;
    x0 += x1; x1 = rotl32(x1, c); x1 ^= x0;
    x0 += x1; x1 = rotl32(x1, d); x1 ^= x0;
}
__device__ __forceinline__ uint32_t jax_bits(uint32_t i) {
    const uint32_t k0 = 0u, k1 = 42u;
    const uint32_t k2 = k0 ^ k1 ^ 0x1BD11BDAu;
    uint32_t x0 = 0u + k0;
    uint32_t x1 = i  + k1;
    tf_r4(x0, x1, 13, 15, 26, 6);   x0 += k1; x1 += k2 + 1u;
    tf_r4(x0, x1, 17, 29, 16, 24);  x0 += k2; x1 += k0 + 2u;
    tf_r4(x0, x1, 13, 15, 26, 6);   x0 += k0; x1 += k1 + 3u;
    tf_r4(x0, x1, 17, 29, 16, 24);  x0 += k1; x1 += k2 + 4u;
    tf_r4(x0, x1, 13, 15, 26, 6);   x0 += k2; x1 += k0 + 5u;
    return x0 ^ x1;
}
__device__ __forceinline__ float gumbel_of(uint32_t lin) {
    uint32_t bits = jax_bits(lin);
    float u = __uint_as_float((bits >> 9) | 0x3f800000u) - 1.0f;
    u = fmaxf(u, 0.f);
    return -logf(-logf(u + 1e-6f) + 1e-6f);
}

// ---------------------------------------------------------------------------
// Kernel B: entmax1.5 bisection + radix-select top-k + exact refinement + TV
// Last block also reduces g_tv -> reg (kernelC folded in).
// ---------------------------------------------------------------------------
#define EPS_W 1.5e-4f
#define MAXC 64
#define SMEM_B ((4*4096 + 32*256)*4)

__global__ __launch_bounds__(1024, 1)
void kernelB(const float* __restrict__ attn, const float* __restrict__ emb,
             const float* __restrict__ gamma_, const float* __restrict__ beta_,
             const float* __restrict__ b2, float* __restrict__ out)
{
    extern __shared__ float sm[];
    float* s_scores = sm;             // 4096
    float* s_attn   = sm + 4096;      // 4096
    float* s_cum    = sm + 8192;      // 4096 (pert)
    float* s_g      = sm + 12288;     // 4096 (g staging for TV)
    float* s_xn     = sm + 16384;     // [32 warps][256]
    __shared__ float red[32], red2[32], red3[32];
    __shared__ float sh_mx, sh_teff, sh_tau, sh_thr, sh_S;
    __shared__ int sh_above, sh_ncand;
    __shared__ int hist[256];
    __shared__ uint32_t sh_prefix;
    __shared__ int sh_remain;
    __shared__ int cand_idx[MAXC];
    __shared__ float cand_pert[MAXC];
    __shared__ int cand_sel[MAXC];

    const int row = blockIdx.x;
    const int tid = threadIdx.x;
    const int lane = tid & 31, wid = tid >> 5;
    const int p0 = tid * 4;

    // ---- load + t_eff + row max
    float tf_ = 0.f, mx = -3.402823466e38f;
    for (int t = tid; t < TT; t += 1024) {
        float s = g_scores[row*TT + t];
        float a = attn[row*TT + t];
        s_scores[t] = s; s_attn[t] = a;
        tf_ += a; mx = fmaxf(mx, s);
    }
    for (int o = 16; o; o >>= 1) {
        tf_ += __shfl_xor_sync(0xffffffffu, tf_, o);
        mx = fmaxf(mx, __shfl_xor_sync(0xffffffffu, mx, o));
    }
    if (lane == 0) { red[wid] = tf_; red2[wid] = mx; }
    __syncthreads();
    if (tid == 0) {
        float a = 0.f, b = -3.402823466e38f;
        for (int w = 0; w < 32; w++) { a += red[w]; b = fmaxf(b, red2[w]); }
        sh_teff = a; sh_mx = b;
        sh_above = 0; sh_ncand = 0;
    }
    __syncthreads();
    mx = sh_mx;

    // ---- entmax tau via bisection on f(tau) = sum max(x-tau,0)^2 (dec.)
    float xr[4];
#pragma unroll
    for (int j = 0; j < 4; ++j) xr[j] = (s_scores[p0+j] - mx) * 0.5f;

    float lo = -1.0f, hi = 0.0f;
    for (int it = 0; it < 28; ++it) {
        float tau = 0.5f*(lo + hi);
        float ssum = 0.f;
#pragma unroll
        for (int j = 0; j < 4; ++j) {
            float d = fmaxf(xr[j] - tau, 0.f);
            ssum += d*d;
        }
        for (int o = 16; o; o >>= 1) ssum += __shfl_xor_sync(0xffffffffu, ssum, o);
        if (lane == 0) red[wid] = ssum;
        __syncthreads();
        if (tid == 0) {
            float a = 0.f;
            for (int w = 0; w < 32; w++) a += red[w];
            sh_S = a;
        }
        __syncthreads();
        if (sh_S > 1.f) lo = tau; else hi = tau;
    }
    // support stats over {x > tau_b}, then exact tau* from the support set
    {
        float taub = 0.5f*(lo + hi);
        float c = 0.f, S1 = 0.f, S2 = 0.f;
#pragma unroll
        for (int j = 0; j < 4; ++j) {
            if (xr[j] > taub) { c += 1.f; S1 += xr[j]; S2 += xr[j]*xr[j]; }
        }
        for (int o = 16; o; o >>= 1) {
            c  += __shfl_xor_sync(0xffffffffu, c, o);
            S1 += __shfl_xor_sync(0xffffffffu, S1, o);
            S2 += __shfl_xor_sync(0xffffffffu, S2, o);
        }
        if (lane == 0) { red[wid] = c; red2[wid] = S1; red3[wid] = S2; }
        __syncthreads();
        if (tid == 0) {
            float cc = 0.f, a1 = 0.f, a2 = 0.f;
            for (int w = 0; w < 32; w++) { cc += red[w]; a1 += red2[w]; a2 += red3[w]; }
            float rho = fmaxf(cc, 1.f);
            float mean = a1 / rho;
            float msq  = a2 / rho;
            float ssv  = rho * (msq - mean*mean);
            float delta = (1.f - ssv) / rho;
            sh_tau = mean - sqrtf(fmaxf(delta, 0.f));
        }
        __syncthreads();
    }
    const float taustar = sh_tau;

    // ---- z output
#pragma unroll
    for (int j = 0; j < 4; ++j) {
        float dd = fmaxf(xr[j] - taustar, 0.f);
        out[row*TT + p0 + j] = dd*dd*s_attn[p0+j];
    }

    // ---- gumbel-perturbed scores (+ radix keys in registers)
    uint32_t ur[4];
#pragma unroll
    for (int j = 0; j < 4; ++j) {
        int t = p0 + j;
        float gum = gumbel_of((uint32_t)(row*TT + t));
        float pert = s_scores[t] * s_attn[t] + gum;
        s_cum[t] = pert;
        uint32_t b = __float_as_uint(pert);
        ur[j] = (pert != pert) ? 0u
              : (b ^ ((b >> 31) ? 0xFFFFFFFFu : 0x80000000u));
    }

    const float teff = sh_teff;
    float kf = rintf(0.3f * teff);
    kf = fminf(fmaxf(kf, 1.f), fmaxf(teff, 1.f));
    const int ki = (int)kf;

    // ---- radix select: exact ki-th largest pert (MSB-first, 8 bits/round)
    if (tid == 0) { sh_prefix = 0u; sh_remain = ki; }
    __syncthreads();
    for (int sha = 24; sha >= 0; sha -= 8) {
        if (tid < 256) hist[tid] = 0;
        __syncthreads();
        uint32_t pref = sh_prefix;
#pragma unroll
        for (int j = 0; j < 4; ++j) {
            uint32_t u = ur[j];
            bool match = (sha == 24) || ((u >> (sha + 8)) == pref);
            if (match) atomicAdd(&hist[(u >> sha) & 255], 1);
        }
        __syncthreads();
        if (wid == 0) {
            int b0 = 255 - lane*8;
            int cnt[8];
            int s = 0;
#pragma unroll
            for (int i = 0; i < 8; i++) { cnt[i] = hist[b0 - i]; s += cnt[i]; }
            int pre = s;
            for (int o = 1; o < 32; o <<= 1) {
                int n = __shfl_up_sync(0xffffffffu, pre, o);
                if (lane >= o) pre += n;
            }
            int excl = pre - s;
            int rem = sh_remain;
            if (excl < rem && rem <= excl + s) {
                int acc = excl;
#pragma unroll
                for (int i = 0; i < 8; i++) {
                    if (acc + cnt[i] >= rem) {
                        uint32_t oldp = sh_prefix;
                        sh_prefix = (oldp << 8) | (uint32_t)(b0 - i);
                        sh_remain = rem - acc;
                        break;
                    }
                    acc += cnt[i];
                }
            }
        }
        __syncthreads();
    }
    if (tid == 0) {
        uint32_t su = sh_prefix;
        uint32_t tb = (su & 0x80000000u) ? (su ^ 0x80000000u) : ~su;
        sh_thr = __uint_as_float(tb);
    }
    __syncthreads();
    const float thr = sh_thr;
    const float hiW = thr + EPS_W, loW = thr - EPS_W;

    // ---- classification counts + candidate gather
    {
        int my_above = 0;
#pragma unroll
        for (int j = 0; j < 4; ++j) {
            int t = p0 + j;
            float p = s_cum[t];
            if (p > hiW) my_above++;
            else if (p >= loW) {
                int pos = atomicAdd(&sh_ncand, 1);
                if (pos < MAXC) cand_idx[pos] = t;
            }
        }
        for (int o = 16; o; o >>= 1) my_above += __shfl_xor_sync(0xffffffffu, my_above, o);
        if (lane == 0) atomicAdd(&sh_above, my_above);
    }
    __syncthreads();
    const int ncand = sh_ncand;
    const bool refine = (ncand <= MAXC);

    // ---- exact recompute of candidate perts (warp per candidate)
    if (refine) {
        const float b2v = b2[0];
        for (int c = wid; c < ncand; c += 32) {
            int t = cand_idx[c];
            float ex;
            if (s_attn[t] == 0.f) {
                ex = s_cum[t];
            } else {
                const float4* e4 = (const float4*)(emb + ((size_t)row*TT + t)*DD);
                float4 va = e4[lane*2], vb = e4[lane*2+1];
                float s  = va.x+va.y+va.z+va.w+vb.x+vb.y+vb.z+vb.w;
                float s2 = va.x*va.x+va.y*va.y+va.z*va.z+va.w*va.w
                         + vb.x*vb.x+vb.y*vb.y+vb.z*vb.z+vb.w*vb.w;
#pragma unroll
                for (int o = 16; o; o >>= 1) {
                    s  += __shfl_xor_sync(0xffffffffu, s, o);
                    s2 += __shfl_xor_sync(0xffffffffu, s2, o);
                }
                float mu = s * (1.f/256.f);
                float rstd = rsqrtf(s2 * (1.f/256.f) - mu*mu + 1e-5f);
                float xv[8] = {va.x,va.y,va.z,va.w,vb.x,vb.y,vb.z,vb.w};
                float* xw = s_xn + wid*256 + lane*8;
#pragma unroll
                for (int p = 0; p < 8; ++p) {
                    int d = lane*8 + p;
                    xw[p] = (xv[p] - mu) * rstd * gamma_[d] + beta_[d];
                }
                __syncwarp();
                float sc = 0.f;
                for (int h = lane; h < HH; h += 32) {
                    const float4* wr = (const float4*)(g_w1t32 + (size_t)h*DD);
                    const float4* xq = (const float4*)(s_xn + wid*256);
                    float dot = 0.f;
#pragma unroll 8
                    for (int u = 0; u < 64; ++u) {
                        float4 a = wr[u], bq = xq[u];
                        dot += a.x*bq.x + a.y*bq.y + a.z*bq.z + a.w*bq.w;
                    }
                    float v = dot + g_b1p[h];
                    sc += gelu_w2(v, g_w2p[h]);
                }
#pragma unroll
                for (int o = 16; o; o >>= 1) sc += __shfl_xor_sync(0xffffffffu, sc, o);
                ex = sc + b2v + gumbel_of((uint32_t)(row*TT + t));
                __syncwarp();
            }
            if (lane == 0) cand_pert[c] = ex;
        }
    }
    __syncthreads();

    if (refine && tid == 0) {
        int need = ki - sh_above;
        for (int c = 0; c < ncand; ++c) {
            int rank = 0;
            float pc = cand_pert[c];
            for (int c2 = 0; c2 < ncand; ++c2)
                if (cand_pert[c2] > pc) rank++;
            cand_sel[c] = (rank < need) ? 1 : 0;
        }
    }
    __syncthreads();

    // ---- g output
#pragma unroll
    for (int j = 0; j < 4; ++j) {
        int t = p0 + j;
        float p = s_cum[t];
        float a0 = s_attn[t];
        float gv;
        if (refine) {
            if (p > hiW) gv = a0;
            else if (p >= loW) {
                gv = 0.f;
                for (int c = 0; c < ncand; ++c)
                    if (cand_idx[c] == t) { gv = cand_sel[c] ? a0 : 0.f; break; }
            } else gv = 0.f;
        } else {
            gv = (p >= thr) ? a0 : 0.f;
        }
        out[BT + row*TT + t] = gv;
        s_g[t] = gv;
    }
    __syncthreads();

    // ---- TV
    float num = 0.f, den = 0.f;
    for (int t = tid; t < TT - 1; t += 1024) {
        float valid = s_attn[t] * s_attn[t+1];
        num += fabsf(s_g[t+1] - s_g[t]) * valid;
        den += valid;
    }
    for (int o = 16; o; o >>= 1) {
        num += __shfl_xor_sync(0xffffffffu, num, o);
        den += __shfl_xor_sync(0xffffffffu, den, o);
    }
    if (lane == 0) { red[wid] = num; red2[wid] = den; }
    __syncthreads();
    if (tid == 0) {
        float a = 0.f, b = 0.f;
        for (int w = 0; w < 32; w++) { a += red[w]; b += red2[w]; }
        g_tv[row] = a / fmaxf(b, 1.f);
        __threadfence();
        int n = atomicAdd(&g_done, 1);
        if (n == BB - 1) {           // last block: reduce + reset counter
            __threadfence();
            float s = 0.f;
            for (int r = 0; r < BB; r++) s += g_tv[r];
            out[2*BT] = 0.1f * (s / (float)BB);
            atomicExch(&g_done, 0);  // replay-deterministic reset
        }
    }
}

extern "C" void kernel_launch(void* const* d_in, const int* in_sizes, int n_in,
                              void* d_out, int out_size)
{
    const float* emb   = (const float*)d_in[0];
    const float* attn  = (const float*)d_in[1];
    const float* gamma = (const float*)d_in[2];
    const float* beta  = (const float*)d_in[3];
    const float* W1    = (const float*)d_in[4];
    const float* b1    = (const float*)d_in[5];
    const float* W2    = (const float*)d_in[6];
    const float* b2    = (const float*)d_in[7];
    float* out = (float*)d_out;

    cudaFuncSetAttribute(kernelA, cudaFuncAttributeMaxDynamicSharedMemorySize, SMEM_A_TOT);
    cudaFuncSetAttribute(kernelB, cudaFuncAttributeMaxDynamicSharedMemorySize, SMEM_B);

    kernelW<<<NP, 256>>>(W1, b1, W2);
    kernelA<<<BT/64, 256, SMEM_A_TOT>>>(emb, attn, gamma, beta, b2);
    kernelB<<<BB, 1024, SMEM_B>>>(attn, emb, gamma, beta, b2, out);
}